// round 2
// baseline (speedup 1.0000x reference)
#include <cuda_runtime.h>
#include <math.h>

// ---------------------------------------------------------------------------
// Problem constants
// ---------------------------------------------------------------------------
#define BB   4
#define NQ_  1024
#define NK_  1024
#define CC   768
#define HH   12
#define DH_  64
#define NTOK (BB * NQ_)      // 4096
#define HID  3072
#define ATT_SCALE 0.125f     // 64^-0.5
#define LNEPS 1e-5f

// ---------------------------------------------------------------------------
// Scratch (device globals: allocation-free, graph-capture safe)
// ---------------------------------------------------------------------------
__device__ float g_xn     [NTOK * CC];
__device__ float g_qkv    [NTOK * 3 * CC];
__device__ float g_sa     [NTOK * CC];
__device__ float g_x1     [NTOK * CC];
__device__ float g_yn     [NTOK * CC];
__device__ float g_cq     [NTOK * CC];
__device__ float g_ck     [NTOK * CC];
__device__ float g_cv     [NTOK * CC];
__device__ float g_x2     [NTOK * CC];
__device__ float g_hid    [NTOK * HID];
__device__ float g_simmean[(size_t)BB * NQ_ * NK_];
__device__ int   g_mask_kind;   // 0 = uint8, 1 = int32, 2 = float32

// ---------------------------------------------------------------------------
// LayerNorm: one block per row of 768, 256 threads (3 elems/thread)
// ---------------------------------------------------------------------------
__global__ __launch_bounds__(256)
void ln_kernel(const float* __restrict__ x, const float* __restrict__ gg,
               const float* __restrict__ bb, float* __restrict__ out)
{
    __shared__ float sh[32];
    int row = blockIdx.x;
    int t = threadIdx.x;
    const float* xr = x + (size_t)row * CC;
    float a0 = xr[t], a1 = xr[t + 256], a2 = xr[t + 512];

    float s = a0 + a1 + a2;
    #pragma unroll
    for (int o = 16; o; o >>= 1) s += __shfl_xor_sync(0xffffffffu, s, o);
    if ((t & 31) == 0) sh[t >> 5] = s;
    __syncthreads();
    if (t < 32) {
        float v = (t < 8) ? sh[t] : 0.f;
        #pragma unroll
        for (int o = 4; o; o >>= 1) v += __shfl_xor_sync(0xffffffffu, v, o);
        if (t == 0) sh[0] = v;
    }
    __syncthreads();
    float mean = sh[0] * (1.0f / CC);
    __syncthreads();

    float d0 = a0 - mean, d1 = a1 - mean, d2 = a2 - mean;
    s = d0 * d0 + d1 * d1 + d2 * d2;
    #pragma unroll
    for (int o = 16; o; o >>= 1) s += __shfl_xor_sync(0xffffffffu, s, o);
    if ((t & 31) == 0) sh[t >> 5] = s;
    __syncthreads();
    if (t < 32) {
        float v = (t < 8) ? sh[t] : 0.f;
        #pragma unroll
        for (int o = 4; o; o >>= 1) v += __shfl_xor_sync(0xffffffffu, v, o);
        if (t == 0) sh[0] = v;
    }
    __syncthreads();
    float rstd = rsqrtf(sh[0] * (1.0f / CC) + LNEPS);

    float* orow = out + (size_t)row * CC;
    orow[t]       = d0 * rstd * gg[t]       + bb[t];
    orow[t + 256] = d1 * rstd * gg[t + 256] + bb[t + 256];
    orow[t + 512] = d2 * rstd * gg[t + 512] + bb[t + 512];
}

// ---------------------------------------------------------------------------
// NT GEMM: C[M,N] = A[M,K] @ W[N,K]^T  (+bias)(+GELU)(+residual)
// BM=128, BN=64, BK=16, 256 threads, 8x4 microtile.
// M multiple of 128, N multiple of 64, K multiple of 16 (all shapes here).
// ---------------------------------------------------------------------------
template<bool GELU>
__global__ __launch_bounds__(256)
void gemm_nt(const float* __restrict__ A, const float* __restrict__ W,
             const float* __restrict__ bias, const float* __restrict__ res,
             float* __restrict__ Cout, int M, int N, int K)
{
    __shared__ float As[16][132];   // [k][m], BM=128 (+4 pad)
    __shared__ float Bs[16][68];    // [k][n], BN=64  (+4 pad)
    int t = threadIdx.x;
    int tx = t & 15, ty = t >> 4;              // tx->N, ty->M
    int m0 = blockIdx.y * 128, n0 = blockIdx.x * 64;

    int arow = t >> 1;            // 0..127
    int ak   = (t & 1) * 8;       // 0 or 8
    int brow = t >> 2;            // 0..63
    int bk   = (t & 3) * 4;       // 0,4,8,12
    const float* Ap = A + (size_t)(m0 + arow) * K + ak;
    const float* Wp = W + (size_t)(n0 + brow) * K + bk;

    float acc[8][4] = {};

    for (int kt = 0; kt < K; kt += 16) {
        float4 a0v = *(const float4*)(Ap + kt);
        float4 a1v = *(const float4*)(Ap + kt + 4);
        float4 wv  = *(const float4*)(Wp + kt);
        As[ak + 0][arow] = a0v.x; As[ak + 1][arow] = a0v.y;
        As[ak + 2][arow] = a0v.z; As[ak + 3][arow] = a0v.w;
        As[ak + 4][arow] = a1v.x; As[ak + 5][arow] = a1v.y;
        As[ak + 6][arow] = a1v.z; As[ak + 7][arow] = a1v.w;
        Bs[bk + 0][brow] = wv.x; Bs[bk + 1][brow] = wv.y;
        Bs[bk + 2][brow] = wv.z; Bs[bk + 3][brow] = wv.w;
        __syncthreads();
        #pragma unroll
        for (int k = 0; k < 16; k++) {
            float4 aA = *(const float4*)&As[k][ty * 8];
            float4 aB = *(const float4*)&As[k][ty * 8 + 4];
            float4 b  = *(const float4*)&Bs[k][tx * 4];
            acc[0][0] += aA.x * b.x; acc[0][1] += aA.x * b.y; acc[0][2] += aA.x * b.z; acc[0][3] += aA.x * b.w;
            acc[1][0] += aA.y * b.x; acc[1][1] += aA.y * b.y; acc[1][2] += aA.y * b.z; acc[1][3] += aA.y * b.w;
            acc[2][0] += aA.z * b.x; acc[2][1] += aA.z * b.y; acc[2][2] += aA.z * b.z; acc[2][3] += aA.z * b.w;
            acc[3][0] += aA.w * b.x; acc[3][1] += aA.w * b.y; acc[3][2] += aA.w * b.z; acc[3][3] += aA.w * b.w;
            acc[4][0] += aB.x * b.x; acc[4][1] += aB.x * b.y; acc[4][2] += aB.x * b.z; acc[4][3] += aB.x * b.w;
            acc[5][0] += aB.y * b.x; acc[5][1] += aB.y * b.y; acc[5][2] += aB.y * b.z; acc[5][3] += aB.y * b.w;
            acc[6][0] += aB.z * b.x; acc[6][1] += aB.z * b.y; acc[6][2] += aB.z * b.z; acc[6][3] += aB.z * b.w;
            acc[7][0] += aB.w * b.x; acc[7][1] += aB.w * b.y; acc[7][2] += aB.w * b.z; acc[7][3] += aB.w * b.w;
        }
        __syncthreads();
    }

    #pragma unroll
    for (int i = 0; i < 8; i++) {
        int row = m0 + ty * 8 + i;
        #pragma unroll
        for (int j = 0; j < 4; j++) {
            int col = n0 + tx * 4 + j;
            float v = acc[i][j];
            if (bias) v += bias[col];
            if (GELU) v = 0.5f * v * (1.0f + erff(v * 0.70710678118654752f));
            if (res)  v += res[(size_t)row * N + col];
            Cout[(size_t)row * N + col] = v;
        }
    }
}

// ---------------------------------------------------------------------------
// Streaming-softmax attention (flash-style), fp32.
// Tile: 64 q-rows x 32 k-cols, DH=64. Grid: (NQ/64, H, B), 256 threads.
// Handles optional cross-attention extras: sims bias (sims - head-mean) + mask.
// ---------------------------------------------------------------------------
__global__ __launch_bounds__(256)
void attn_kernel(const float* __restrict__ Qb, const float* __restrict__ Kb,
                 const float* __restrict__ Vb,
                 int q_rs, int kv_rs,
                 long long q_bs, long long q_hoff,
                 long long kv_bs, long long kv_hoff,
                 float* __restrict__ Ob,
                 const float* __restrict__ sims,
                 const float* __restrict__ simmean,
                 const void* __restrict__ maskp)
{
    __shared__ float Qst[64][68];   // [d][r]
    __shared__ float Kst[64][36];   // [d][c], c in 0..31
    __shared__ float Vs [32][68];   // [kk][d]
    __shared__ float Ps [64][33];   // [r][kk]
    __shared__ float rowm[64], rowl[64], rowa[64];

    int t = threadIdx.x;
    int tx = t & 15, ty = t >> 4;
    int b = blockIdx.z, h = blockIdx.y;
    int q0 = blockIdx.x * 64;

    const float* Qp = Qb + (long long)b * q_bs  + (long long)h * q_hoff;
    const float* Kp = Kb + (long long)b * kv_bs + (long long)h * kv_hoff;
    const float* Vp = Vb + (long long)b * kv_bs + (long long)h * kv_hoff;

    for (int idx = t; idx < 4096; idx += 256) {
        int n = idx >> 6, d = idx & 63;
        Qst[d][n] = Qp[(size_t)(q0 + n) * q_rs + d];
    }
    if (t < 64) { rowm[t] = -1e30f; rowl[t] = 0.f; }

    float acc[4][4] = {};
    const bool cross = (sims != nullptr);
    const int mkind = cross ? g_mask_kind : 0;
    const unsigned char* mu8 = (const unsigned char*)maskp;
    const int*   mi32 = (const int*)maskp;
    const float* mf32 = (const float*)maskp;
    __syncthreads();

    for (int k0 = 0; k0 < NK_; k0 += 32) {
        for (int idx = t; idx < 2048; idx += 256) {
            int c = idx >> 6, d = idx & 63;
            Kst[d][c] = Kp[(size_t)(k0 + c) * kv_rs + d];
        }
        for (int idx = t; idx < 2048; idx += 256) {
            int kk = idx >> 6, d = idx & 63;
            Vs[kk][d] = Vp[(size_t)(k0 + kk) * kv_rs + d];
        }
        __syncthreads();

        // S = (Q K^T) * scale  (+ bias, mask)
        float s[4][2] = {};
        #pragma unroll
        for (int d = 0; d < 64; d++) {
            float4 a = *(const float4*)&Qst[d][ty * 4];
            float b0 = Kst[d][tx * 2], b1 = Kst[d][tx * 2 + 1];
            s[0][0] += a.x * b0; s[0][1] += a.x * b1;
            s[1][0] += a.y * b0; s[1][1] += a.y * b1;
            s[2][0] += a.z * b0; s[2][1] += a.z * b1;
            s[3][0] += a.w * b0; s[3][1] += a.w * b1;
        }
        #pragma unroll
        for (int i = 0; i < 4; i++) {
            #pragma unroll
            for (int j = 0; j < 2; j++) {
                int q = q0 + ty * 4 + i, k = k0 + tx * 2 + j;
                float v = s[i][j] * ATT_SCALE;
                if (cross) {
                    size_t si = ((size_t)(b * HH + h) * NQ_ + q) * NK_ + k;
                    v += sims[si] - simmean[((size_t)b * NQ_ + q) * NK_ + k];
                    size_t mi = (size_t)q * NK_ + k;
                    bool keep = (mkind == 0) ? (mu8[mi] != 0)
                              : (mkind == 1) ? (mi32[mi] != 0)
                                             : (mf32[mi] != 0.f);
                    if (!keep) v = -1e30f;
                }
                Ps[ty * 4 + i][tx * 2 + j] = v;
            }
        }
        __syncthreads();

        // online softmax, row-per-thread
        if (t < 64) {
            float mo = rowm[t];
            float mx = mo;
            #pragma unroll 8
            for (int c = 0; c < 32; c++) mx = fmaxf(mx, Ps[t][c]);
            float alpha, sum = 0.f;
            if (mx <= -1e29f) {
                alpha = 1.f;
                #pragma unroll 8
                for (int c = 0; c < 32; c++) Ps[t][c] = 0.f;
            } else {
                alpha = __expf(mo - mx);
                #pragma unroll 8
                for (int c = 0; c < 32; c++) {
                    float p = __expf(Ps[t][c] - mx);
                    Ps[t][c] = p; sum += p;
                }
            }
            rowm[t] = mx;
            rowl[t] = rowl[t] * alpha + sum;
            rowa[t] = alpha;
        }
        __syncthreads();

        float al[4];
        #pragma unroll
        for (int i = 0; i < 4; i++) al[i] = rowa[ty * 4 + i];
        #pragma unroll
        for (int i = 0; i < 4; i++) {
            acc[i][0] *= al[i]; acc[i][1] *= al[i];
            acc[i][2] *= al[i]; acc[i][3] *= al[i];
        }
        // O += P @ V  (cols = tx*4..+3 of DH)
        #pragma unroll
        for (int kk = 0; kk < 32; kk++) {
            float4 v = *(const float4*)&Vs[kk][tx * 4];
            float p0 = Ps[ty * 4 + 0][kk], p1 = Ps[ty * 4 + 1][kk];
            float p2 = Ps[ty * 4 + 2][kk], p3 = Ps[ty * 4 + 3][kk];
            acc[0][0] += p0 * v.x; acc[0][1] += p0 * v.y; acc[0][2] += p0 * v.z; acc[0][3] += p0 * v.w;
            acc[1][0] += p1 * v.x; acc[1][1] += p1 * v.y; acc[1][2] += p1 * v.z; acc[1][3] += p1 * v.w;
            acc[2][0] += p2 * v.x; acc[2][1] += p2 * v.y; acc[2][2] += p2 * v.z; acc[2][3] += p2 * v.w;
            acc[3][0] += p3 * v.x; acc[3][1] += p3 * v.y; acc[3][2] += p3 * v.z; acc[3][3] += p3 * v.w;
        }
        __syncthreads();
    }

    #pragma unroll
    for (int i = 0; i < 4; i++) {
        int q = q0 + ty * 4 + i;
        float inv = 1.f / rowl[ty * 4 + i];
        float* op = Ob + ((size_t)b * NQ_ + q) * CC + h * DH_ + tx * 4;
        op[0] = acc[i][0] * inv; op[1] = acc[i][1] * inv;
        op[2] = acc[i][2] * inv; op[3] = acc[i][3] * inv;
    }
}

// ---------------------------------------------------------------------------
// similarities head-mean: g_simmean[b,q,k] = mean_h sims[b,h,q,k]
// ---------------------------------------------------------------------------
__global__ __launch_bounds__(256)
void simmean_kernel(const float* __restrict__ sims)
{
    size_t idx = (size_t)blockIdx.x * 256 + threadIdx.x;   // 0 .. 4*2^20-1
    int b = (int)(idx >> 20);
    size_t qk = idx & 1048575u;
    float s = 0.f;
    #pragma unroll
    for (int h = 0; h < HH; h++)
        s += sims[(((size_t)(b * HH + h)) << 20) + qk];
    g_simmean[idx] = s * (1.0f / HH);
}

// ---------------------------------------------------------------------------
// Mask dtype detection (u8 vs i32 vs f32 storage of bool). Deterministic.
// ---------------------------------------------------------------------------
__global__ void detect_mask_kernel(const unsigned char* __restrict__ m)
{
    if (threadIdx.x == 0 && blockIdx.x == 0) {
        int ones = 0, nonbin = 0;
        for (int i = 0; i < 4096; i++) {
            unsigned char v = m[i];
            if (v > 1) nonbin = 1;
            if (v == 1) ones++;
        }
        // u8 bool: ~50% of 4096 bytes are 1. i32 bool: 1s appear only every
        // 4th byte (little-endian) -> <=1024. f32 bool: bytes include 0x80/0x3f.
        g_mask_kind = nonbin ? 2 : (ones > 1228 ? 0 : 1);
    }
}

// ---------------------------------------------------------------------------
// float4 copy (y passthrough into second half of output)
// ---------------------------------------------------------------------------
__global__ __launch_bounds__(256)
void copy4_kernel(const float4* __restrict__ s, float4* __restrict__ d, int n4)
{
    int i = blockIdx.x * 256 + threadIdx.x;
    if (i < n4) d[i] = s[i];
}

// ---------------------------------------------------------------------------
// Launch
// ---------------------------------------------------------------------------
extern "C" void kernel_launch(void* const* d_in, const int* in_sizes, int n_in,
                              void* d_out, int out_size)
{
    const float* x       = (const float*)d_in[0];
    const float* y       = (const float*)d_in[1];
    // d_in[2]=xpos, d_in[3]=ypos : unused by reference
    const void*  mask    = d_in[4];
    const float* sims    = (const float*)d_in[5];
    const float* ln1_g   = (const float*)d_in[6];
    const float* ln1_b   = (const float*)d_in[7];
    const float* ln2_g   = (const float*)d_in[8];
    const float* ln2_b   = (const float*)d_in[9];
    const float* ln3_g   = (const float*)d_in[10];
    const float* ln3_b   = (const float*)d_in[11];
    const float* lny_g   = (const float*)d_in[12];
    const float* lny_b   = (const float*)d_in[13];
    const float* qkv_w   = (const float*)d_in[14];
    const float* aproj_w = (const float*)d_in[15];
    const float* aproj_b = (const float*)d_in[16];
    const float* pq_w    = (const float*)d_in[17];
    const float* pk_w    = (const float*)d_in[18];
    const float* pv_w    = (const float*)d_in[19];
    const float* cproj_w = (const float*)d_in[20];
    const float* cproj_b = (const float*)d_in[21];
    const float* fc1_w   = (const float*)d_in[22];
    const float* fc1_b   = (const float*)d_in[23];
    const float* fc2_w   = (const float*)d_in[24];
    const float* fc2_b   = (const float*)d_in[25];
    float* out = (float*)d_out;

    float *p_xn, *p_qkv, *p_sa, *p_x1, *p_yn, *p_cq, *p_ck, *p_cv, *p_x2, *p_hid, *p_sm;
    cudaGetSymbolAddress((void**)&p_xn,  g_xn);
    cudaGetSymbolAddress((void**)&p_qkv, g_qkv);
    cudaGetSymbolAddress((void**)&p_sa,  g_sa);
    cudaGetSymbolAddress((void**)&p_x1,  g_x1);
    cudaGetSymbolAddress((void**)&p_yn,  g_yn);
    cudaGetSymbolAddress((void**)&p_cq,  g_cq);
    cudaGetSymbolAddress((void**)&p_ck,  g_ck);
    cudaGetSymbolAddress((void**)&p_cv,  g_cv);
    cudaGetSymbolAddress((void**)&p_x2,  g_x2);
    cudaGetSymbolAddress((void**)&p_hid, g_hid);
    cudaGetSymbolAddress((void**)&p_sm,  g_simmean);

    // ---- self-attention ----
    ln_kernel<<<NTOK, 256>>>(x, ln1_g, ln1_b, p_xn);
    gemm_nt<false><<<dim3(3 * CC / 64, NTOK / 128), 256>>>(
        p_xn, qkv_w, nullptr, nullptr, p_qkv, NTOK, 3 * CC, CC);
    attn_kernel<<<dim3(NQ_ / 64, HH, BB), 256>>>(
        p_qkv, p_qkv + CC, p_qkv + 2 * CC,
        3 * CC, 3 * CC,
        (long long)NQ_ * 3 * CC, DH_,
        (long long)NQ_ * 3 * CC, DH_,
        p_sa, nullptr, nullptr, nullptr);
    gemm_nt<false><<<dim3(CC / 64, NTOK / 128), 256>>>(
        p_sa, aproj_w, aproj_b, x, p_x1, NTOK, CC, CC);

    // ---- cross-attention ----
    ln_kernel<<<NTOK, 256>>>(y,    lny_g, lny_b, p_yn);
    ln_kernel<<<NTOK, 256>>>(p_x1, ln2_g, ln2_b, p_xn);
    gemm_nt<false><<<dim3(CC / 64, NTOK / 128), 256>>>(
        p_xn, pq_w, nullptr, nullptr, p_cq, NTOK, CC, CC);
    gemm_nt<false><<<dim3(CC / 64, NTOK / 128), 256>>>(
        p_yn, pk_w, nullptr, nullptr, p_ck, NTOK, CC, CC);
    gemm_nt<false><<<dim3(CC / 64, NTOK / 128), 256>>>(
        p_yn, pv_w, nullptr, nullptr, p_cv, NTOK, CC, CC);
    simmean_kernel<<<(BB * NQ_ * NK_) / 256, 256>>>(sims);
    detect_mask_kernel<<<1, 1>>>((const unsigned char*)mask);
    attn_kernel<<<dim3(NQ_ / 64, HH, BB), 256>>>(
        p_cq, p_ck, p_cv,
        CC, CC,
        (long long)NQ_ * CC, DH_,
        (long long)NQ_ * CC, DH_,
        p_sa, sims, p_sm, mask);
    gemm_nt<false><<<dim3(CC / 64, NTOK / 128), 256>>>(
        p_sa, cproj_w, cproj_b, p_x1, p_x2, NTOK, CC, CC);

    // ---- MLP ----
    ln_kernel<<<NTOK, 256>>>(p_x2, ln3_g, ln3_b, p_xn);
    gemm_nt<true><<<dim3(HID / 64, NTOK / 128), 256>>>(
        p_xn, fc1_w, fc1_b, nullptr, p_hid, NTOK, HID, CC);
    gemm_nt<false><<<dim3(CC / 64, NTOK / 128), 256>>>(
        p_hid, fc2_w, fc2_b, p_x2, out, NTOK, CC, HID);

    // ---- y passthrough (second half of output), only if out holds (x, y) ----
    if (out_size >= 2 * NTOK * CC) {
        copy4_kernel<<<(NTOK * CC / 4 + 255) / 256, 256>>>(
            (const float4*)y, (float4*)(out + (size_t)NTOK * CC), NTOK * CC / 4);
    }
}

// round 4
// speedup vs baseline: 1.5268x; 1.5268x over previous
#include <cuda_runtime.h>
#include <math.h>
#include <stdint.h>

// ---------------------------------------------------------------------------
// Problem constants
// ---------------------------------------------------------------------------
#define BB   4
#define NQ_  1024
#define NK_  1024
#define CC   768
#define HH   12
#define DH_  64
#define NTOK (BB * NQ_)      // 4096
#define HID  3072
#define ATT_SCALE 0.125f     // 64^-0.5
#define LNEPS 1e-5f

// ---------------------------------------------------------------------------
// Scratch (device globals: allocation-free, graph-capture safe)
// ---------------------------------------------------------------------------
__device__ float g_xn     [NTOK * CC];
__device__ float g_qkv    [NTOK * 3 * CC];
__device__ float g_sa     [NTOK * CC];
__device__ float g_x1     [NTOK * CC];
__device__ float g_yn     [NTOK * CC];
__device__ float g_cq     [NTOK * CC];
__device__ float g_ck     [NTOK * CC];
__device__ float g_cv     [NTOK * CC];
__device__ float g_x2     [NTOK * CC];
__device__ float g_hid    [NTOK * HID];
__device__ float g_simmean[(size_t)BB * NQ_ * NK_];
__device__ int   g_mask_kind;   // 0 = uint8, 1 = int32, 2 = float32

// ---------------------------------------------------------------------------
// tf32 helpers
// ---------------------------------------------------------------------------
__device__ __forceinline__ uint32_t f2tf32(float x) {
    uint32_t u;
    asm("cvt.rna.tf32.f32 %0, %1;" : "=r"(u) : "f"(x));
    return u;
}

__device__ __forceinline__ void mma_tf32(float* c, const uint32_t* a, const uint32_t* b) {
    asm volatile(
        "mma.sync.aligned.m16n8k8.row.col.f32.tf32.tf32.f32 "
        "{%0,%1,%2,%3}, {%4,%5,%6,%7}, {%8,%9}, {%0,%1,%2,%3};"
        : "+f"(c[0]), "+f"(c[1]), "+f"(c[2]), "+f"(c[3])
        : "r"(a[0]), "r"(a[1]), "r"(a[2]), "r"(a[3]), "r"(b[0]), "r"(b[1]));
}

// ---------------------------------------------------------------------------
// LayerNorm: one block per row of 768, 256 threads (3 elems/thread)
// ---------------------------------------------------------------------------
__global__ __launch_bounds__(256)
void ln_kernel(const float* __restrict__ x, const float* __restrict__ gg,
               const float* __restrict__ bb, float* __restrict__ out)
{
    __shared__ float sh[32];
    int row = blockIdx.x;
    int t = threadIdx.x;
    const float* xr = x + (size_t)row * CC;
    float a0 = xr[t], a1 = xr[t + 256], a2 = xr[t + 512];

    float s = a0 + a1 + a2;
    #pragma unroll
    for (int o = 16; o; o >>= 1) s += __shfl_xor_sync(0xffffffffu, s, o);
    if ((t & 31) == 0) sh[t >> 5] = s;
    __syncthreads();
    if (t < 32) {
        float v = (t < 8) ? sh[t] : 0.f;
        #pragma unroll
        for (int o = 4; o; o >>= 1) v += __shfl_xor_sync(0xffffffffu, v, o);
        if (t == 0) sh[0] = v;
    }
    __syncthreads();
    float mean = sh[0] * (1.0f / CC);
    __syncthreads();

    float d0 = a0 - mean, d1 = a1 - mean, d2 = a2 - mean;
    s = d0 * d0 + d1 * d1 + d2 * d2;
    #pragma unroll
    for (int o = 16; o; o >>= 1) s += __shfl_xor_sync(0xffffffffu, s, o);
    if ((t & 31) == 0) sh[t >> 5] = s;
    __syncthreads();
    if (t < 32) {
        float v = (t < 8) ? sh[t] : 0.f;
        #pragma unroll
        for (int o = 4; o; o >>= 1) v += __shfl_xor_sync(0xffffffffu, v, o);
        if (t == 0) sh[0] = v;
    }
    __syncthreads();
    float rstd = rsqrtf(sh[0] * (1.0f / CC) + LNEPS);

    float* orow = out + (size_t)row * CC;
    orow[t]       = d0 * rstd * gg[t]       + bb[t];
    orow[t + 256] = d1 * rstd * gg[t + 256] + bb[t + 256];
    orow[t + 512] = d2 * rstd * gg[t + 512] + bb[t + 512];
}

// ---------------------------------------------------------------------------
// Tensor-core NT GEMM (tf32): C[M,N] = A[M,K] @ W[N,K]^T (+bias)(+GELU)(+res)
// BM=BN=128, BK=32, 256 threads / 8 warps (2x4), warp tile 64x32,
// fragments m16n8k8, fp32 accumulate. M%128==0, N%128==0, K%32==0.
// ---------------------------------------------------------------------------
template<bool GELU>
__global__ __launch_bounds__(256)
void gemm_tc(const float* __restrict__ A, const float* __restrict__ W,
             const float* __restrict__ bias, const float* __restrict__ res,
             float* __restrict__ Cout, int M, int N, int K)
{
    __shared__ uint32_t As[128][36];   // [m][k] tf32 bits (+4 pad)
    __shared__ uint32_t Bs[128][36];   // [n][k] tf32 bits (+4 pad)

    int t = threadIdx.x;
    int lane = t & 31, wid = t >> 5;
    int warp_m = wid >> 2;            // 0..1
    int warp_n = wid & 3;             // 0..3
    int m0 = blockIdx.y * 128, n0 = blockIdx.x * 128;

    int lrow = t >> 1;                // 0..127
    int lf   = (t & 1) * 4;           // float4 slot base: 0 or 4
    const float4* Ap = (const float4*)(A + (size_t)(m0 + lrow) * K);
    const float4* Wp = (const float4*)(W + (size_t)(n0 + lrow) * K);

    float acc[4][4][4];
    #pragma unroll
    for (int i = 0; i < 4; i++)
        #pragma unroll
        for (int j = 0; j < 4; j++)
            #pragma unroll
            for (int r = 0; r < 4; r++) acc[i][j][r] = 0.f;

    // prefetch first tile
    float4 ar[4], br[4];
    #pragma unroll
    for (int j = 0; j < 4; j++) { ar[j] = Ap[lf + j]; br[j] = Wp[lf + j]; }

    for (int kt = 0; kt < K; kt += 32) {
        // store prefetched tile (tf32-rounded)
        #pragma unroll
        for (int j = 0; j < 4; j++) {
            int c = (lf + j) * 4;
            As[lrow][c + 0] = f2tf32(ar[j].x); As[lrow][c + 1] = f2tf32(ar[j].y);
            As[lrow][c + 2] = f2tf32(ar[j].z); As[lrow][c + 3] = f2tf32(ar[j].w);
            Bs[lrow][c + 0] = f2tf32(br[j].x); Bs[lrow][c + 1] = f2tf32(br[j].y);
            Bs[lrow][c + 2] = f2tf32(br[j].z); Bs[lrow][c + 3] = f2tf32(br[j].w);
        }
        __syncthreads();

        if (kt + 32 < K) {
            int kt4 = (kt + 32) >> 2;
            #pragma unroll
            for (int j = 0; j < 4; j++) { ar[j] = Ap[kt4 + lf + j]; br[j] = Wp[kt4 + lf + j]; }
        }

        #pragma unroll
        for (int k8 = 0; k8 < 32; k8 += 8) {
            uint32_t af[4][4], bf[4][2];
            int c0 = k8 + (lane & 3);
            #pragma unroll
            for (int mt = 0; mt < 4; mt++) {
                int r = warp_m * 64 + mt * 16 + (lane >> 2);
                af[mt][0] = As[r    ][c0];
                af[mt][1] = As[r + 8][c0];
                af[mt][2] = As[r    ][c0 + 4];
                af[mt][3] = As[r + 8][c0 + 4];
            }
            #pragma unroll
            for (int nt = 0; nt < 4; nt++) {
                int n = warp_n * 32 + nt * 8 + (lane >> 2);
                bf[nt][0] = Bs[n][c0];
                bf[nt][1] = Bs[n][c0 + 4];
            }
            #pragma unroll
            for (int mt = 0; mt < 4; mt++)
                #pragma unroll
                for (int nt = 0; nt < 4; nt++)
                    mma_tf32(acc[mt][nt], af[mt], bf[nt]);
        }
        __syncthreads();
    }

    // epilogue
    #pragma unroll
    for (int mt = 0; mt < 4; mt++) {
        int row0 = m0 + warp_m * 64 + mt * 16 + (lane >> 2);
        #pragma unroll
        for (int nt = 0; nt < 4; nt++) {
            int col = n0 + warp_n * 32 + nt * 8 + (lane & 3) * 2;
            float b0 = bias ? bias[col]     : 0.f;
            float b1 = bias ? bias[col + 1] : 0.f;

            float v00 = acc[mt][nt][0] + b0, v01 = acc[mt][nt][1] + b1;
            float v10 = acc[mt][nt][2] + b0, v11 = acc[mt][nt][3] + b1;
            if (GELU) {
                v00 = 0.5f * v00 * (1.0f + erff(v00 * 0.70710678118654752f));
                v01 = 0.5f * v01 * (1.0f + erff(v01 * 0.70710678118654752f));
                v10 = 0.5f * v10 * (1.0f + erff(v10 * 0.70710678118654752f));
                v11 = 0.5f * v11 * (1.0f + erff(v11 * 0.70710678118654752f));
            }
            if (res) {
                v00 += res[(size_t)row0 * N + col];
                v01 += res[(size_t)row0 * N + col + 1];
                v10 += res[(size_t)(row0 + 8) * N + col];
                v11 += res[(size_t)(row0 + 8) * N + col + 1];
            }
            *(float2*)&Cout[(size_t)row0 * N + col]       = make_float2(v00, v01);
            *(float2*)&Cout[(size_t)(row0 + 8) * N + col] = make_float2(v10, v11);
        }
    }
}

// ---------------------------------------------------------------------------
// Streaming-softmax attention (flash-style), fp32.
// Tile: 64 q-rows x 32 k-cols, DH=64. Grid: (NQ/64, H, B), 256 threads.
// Handles optional cross-attention extras: sims bias (sims - head-mean) + mask.
// ---------------------------------------------------------------------------
__global__ __launch_bounds__(256)
void attn_kernel(const float* __restrict__ Qb, const float* __restrict__ Kb,
                 const float* __restrict__ Vb,
                 int q_rs, int kv_rs,
                 long long q_bs, long long q_hoff,
                 long long kv_bs, long long kv_hoff,
                 float* __restrict__ Ob,
                 const float* __restrict__ sims,
                 const float* __restrict__ simmean,
                 const void* __restrict__ maskp)
{
    __shared__ float Qst[64][68];   // [d][r]
    __shared__ float Kst[64][36];   // [d][c], c in 0..31
    __shared__ float Vs [32][68];   // [kk][d]
    __shared__ float Ps [64][33];   // [r][kk]
    __shared__ float rowm[64], rowl[64], rowa[64];

    int t = threadIdx.x;
    int tx = t & 15, ty = t >> 4;
    int b = blockIdx.z, h = blockIdx.y;
    int q0 = blockIdx.x * 64;

    const float* Qp = Qb + (long long)b * q_bs  + (long long)h * q_hoff;
    const float* Kp = Kb + (long long)b * kv_bs + (long long)h * kv_hoff;
    const float* Vp = Vb + (long long)b * kv_bs + (long long)h * kv_hoff;

    for (int idx = t; idx < 4096; idx += 256) {
        int n = idx >> 6, d = idx & 63;
        Qst[d][n] = Qp[(size_t)(q0 + n) * q_rs + d];
    }
    if (t < 64) { rowm[t] = -1e30f; rowl[t] = 0.f; }

    float acc[4][4] = {};
    const bool cross = (sims != nullptr);
    const int mkind = cross ? g_mask_kind : 0;
    const unsigned char* mu8 = (const unsigned char*)maskp;
    const int*   mi32 = (const int*)maskp;
    const float* mf32 = (const float*)maskp;
    __syncthreads();

    for (int k0 = 0; k0 < NK_; k0 += 32) {
        for (int idx = t; idx < 2048; idx += 256) {
            int c = idx >> 6, d = idx & 63;
            Kst[d][c] = Kp[(size_t)(k0 + c) * kv_rs + d];
        }
        for (int idx = t; idx < 2048; idx += 256) {
            int kk = idx >> 6, d = idx & 63;
            Vs[kk][d] = Vp[(size_t)(k0 + kk) * kv_rs + d];
        }
        __syncthreads();

        // S = (Q K^T) * scale  (+ bias, mask)
        float s[4][2] = {};
        #pragma unroll
        for (int d = 0; d < 64; d++) {
            float4 a = *(const float4*)&Qst[d][ty * 4];
            float b0 = Kst[d][tx * 2], b1 = Kst[d][tx * 2 + 1];
            s[0][0] += a.x * b0; s[0][1] += a.x * b1;
            s[1][0] += a.y * b0; s[1][1] += a.y * b1;
            s[2][0] += a.z * b0; s[2][1] += a.z * b1;
            s[3][0] += a.w * b0; s[3][1] += a.w * b1;
        }
        #pragma unroll
        for (int i = 0; i < 4; i++) {
            #pragma unroll
            for (int j = 0; j < 2; j++) {
                int q = q0 + ty * 4 + i, k = k0 + tx * 2 + j;
                float v = s[i][j] * ATT_SCALE;
                if (cross) {
                    size_t si = ((size_t)(b * HH + h) * NQ_ + q) * NK_ + k;
                    v += sims[si] - simmean[((size_t)b * NQ_ + q) * NK_ + k];
                    size_t mi = (size_t)q * NK_ + k;
                    bool keep = (mkind == 0) ? (mu8[mi] != 0)
                              : (mkind == 1) ? (mi32[mi] != 0)
                                             : (mf32[mi] != 0.f);
                    if (!keep) v = -1e30f;
                }
                Ps[ty * 4 + i][tx * 2 + j] = v;
            }
        }
        __syncthreads();

        // online softmax, row-per-thread
        if (t < 64) {
            float mo = rowm[t];
            float mx = mo;
            #pragma unroll 8
            for (int c = 0; c < 32; c++) mx = fmaxf(mx, Ps[t][c]);
            float alpha, sum = 0.f;
            if (mx <= -1e29f) {
                alpha = 1.f;
                #pragma unroll 8
                for (int c = 0; c < 32; c++) Ps[t][c] = 0.f;
            } else {
                alpha = __expf(mo - mx);
                #pragma unroll 8
                for (int c = 0; c < 32; c++) {
                    float p = __expf(Ps[t][c] - mx);
                    Ps[t][c] = p; sum += p;
                }
            }
            rowm[t] = mx;
            rowl[t] = rowl[t] * alpha + sum;
            rowa[t] = alpha;
        }
        __syncthreads();

        float al[4];
        #pragma unroll
        for (int i = 0; i < 4; i++) al[i] = rowa[ty * 4 + i];
        #pragma unroll
        for (int i = 0; i < 4; i++) {
            acc[i][0] *= al[i]; acc[i][1] *= al[i];
            acc[i][2] *= al[i]; acc[i][3] *= al[i];
        }
        // O += P @ V  (cols = tx*4..+3 of DH)
        #pragma unroll
        for (int kk = 0; kk < 32; kk++) {
            float4 v = *(const float4*)&Vs[kk][tx * 4];
            float p0 = Ps[ty * 4 + 0][kk], p1 = Ps[ty * 4 + 1][kk];
            float p2 = Ps[ty * 4 + 2][kk], p3 = Ps[ty * 4 + 3][kk];
            acc[0][0] += p0 * v.x; acc[0][1] += p0 * v.y; acc[0][2] += p0 * v.z; acc[0][3] += p0 * v.w;
            acc[1][0] += p1 * v.x; acc[1][1] += p1 * v.y; acc[1][2] += p1 * v.z; acc[1][3] += p1 * v.w;
            acc[2][0] += p2 * v.x; acc[2][1] += p2 * v.y; acc[2][2] += p2 * v.z; acc[2][3] += p2 * v.w;
            acc[3][0] += p3 * v.x; acc[3][1] += p3 * v.y; acc[3][2] += p3 * v.z; acc[3][3] += p3 * v.w;
        }
        __syncthreads();
    }

    #pragma unroll
    for (int i = 0; i < 4; i++) {
        int q = q0 + ty * 4 + i;
        float inv = 1.f / rowl[ty * 4 + i];
        float* op = Ob + ((size_t)b * NQ_ + q) * CC + h * DH_ + tx * 4;
        op[0] = acc[i][0] * inv; op[1] = acc[i][1] * inv;
        op[2] = acc[i][2] * inv; op[3] = acc[i][3] * inv;
    }
}

// ---------------------------------------------------------------------------
// similarities head-mean: g_simmean[b,q,k] = mean_h sims[b,h,q,k]
// ---------------------------------------------------------------------------
__global__ __launch_bounds__(256)
void simmean_kernel(const float* __restrict__ sims)
{
    size_t idx = (size_t)blockIdx.x * 256 + threadIdx.x;   // 0 .. 4*2^20-1
    int b = (int)(idx >> 20);
    size_t qk = idx & 1048575u;
    float s = 0.f;
    #pragma unroll
    for (int h = 0; h < HH; h++)
        s += sims[(((size_t)(b * HH + h)) << 20) + qk];
    g_simmean[idx] = s * (1.0f / HH);
}

// ---------------------------------------------------------------------------
// Mask dtype detection (u8 vs i32 vs f32 storage of bool). Deterministic.
// ---------------------------------------------------------------------------
__global__ void detect_mask_kernel(const unsigned char* __restrict__ m)
{
    if (threadIdx.x == 0 && blockIdx.x == 0) {
        int ones = 0, nonbin = 0;
        for (int i = 0; i < 4096; i++) {
            unsigned char v = m[i];
            if (v > 1) nonbin = 1;
            if (v == 1) ones++;
        }
        g_mask_kind = nonbin ? 2 : (ones > 1228 ? 0 : 1);
    }
}

// ---------------------------------------------------------------------------
// float4 copy (y passthrough into second half of output)
// ---------------------------------------------------------------------------
__global__ __launch_bounds__(256)
void copy4_kernel(const float4* __restrict__ s, float4* __restrict__ d, int n4)
{
    int i = blockIdx.x * 256 + threadIdx.x;
    if (i < n4) d[i] = s[i];
}

// ---------------------------------------------------------------------------
// Launch
// ---------------------------------------------------------------------------
extern "C" void kernel_launch(void* const* d_in, const int* in_sizes, int n_in,
                              void* d_out, int out_size)
{
    const float* x       = (const float*)d_in[0];
    const float* y       = (const float*)d_in[1];
    const void*  mask    = d_in[4];
    const float* sims    = (const float*)d_in[5];
    const float* ln1_g   = (const float*)d_in[6];
    const float* ln1_b   = (const float*)d_in[7];
    const float* ln2_g   = (const float*)d_in[8];
    const float* ln2_b   = (const float*)d_in[9];
    const float* ln3_g   = (const float*)d_in[10];
    const float* ln3_b   = (const float*)d_in[11];
    const float* lny_g   = (const float*)d_in[12];
    const float* lny_b   = (const float*)d_in[13];
    const float* qkv_w   = (const float*)d_in[14];
    const float* aproj_w = (const float*)d_in[15];
    const float* aproj_b = (const float*)d_in[16];
    const float* pq_w    = (const float*)d_in[17];
    const float* pk_w    = (const float*)d_in[18];
    const float* pv_w    = (const float*)d_in[19];
    const float* cproj_w = (const float*)d_in[20];
    const float* cproj_b = (const float*)d_in[21];
    const float* fc1_w   = (const float*)d_in[22];
    const float* fc1_b   = (const float*)d_in[23];
    const float* fc2_w   = (const float*)d_in[24];
    const float* fc2_b   = (const float*)d_in[25];
    float* out = (float*)d_out;

    float *p_xn, *p_qkv, *p_sa, *p_x1, *p_yn, *p_cq, *p_ck, *p_cv, *p_x2, *p_hid, *p_sm;
    cudaGetSymbolAddress((void**)&p_xn,  g_xn);
    cudaGetSymbolAddress((void**)&p_qkv, g_qkv);
    cudaGetSymbolAddress((void**)&p_sa,  g_sa);
    cudaGetSymbolAddress((void**)&p_x1,  g_x1);
    cudaGetSymbolAddress((void**)&p_yn,  g_yn);
    cudaGetSymbolAddress((void**)&p_cq,  g_cq);
    cudaGetSymbolAddress((void**)&p_ck,  g_ck);
    cudaGetSymbolAddress((void**)&p_cv,  g_cv);
    cudaGetSymbolAddress((void**)&p_x2,  g_x2);
    cudaGetSymbolAddress((void**)&p_hid, g_hid);
    cudaGetSymbolAddress((void**)&p_sm,  g_simmean);

    // ---- self-attention ----
    ln_kernel<<<NTOK, 256>>>(x, ln1_g, ln1_b, p_xn);
    gemm_tc<false><<<dim3(3 * CC / 128, NTOK / 128), 256>>>(
        p_xn, qkv_w, nullptr, nullptr, p_qkv, NTOK, 3 * CC, CC);
    attn_kernel<<<dim3(NQ_ / 64, HH, BB), 256>>>(
        p_qkv, p_qkv + CC, p_qkv + 2 * CC,
        3 * CC, 3 * CC,
        (long long)NQ_ * 3 * CC, DH_,
        (long long)NQ_ * 3 * CC, DH_,
        p_sa, nullptr, nullptr, nullptr);
    gemm_tc<false><<<dim3(CC / 128, NTOK / 128), 256>>>(
        p_sa, aproj_w, aproj_b, x, p_x1, NTOK, CC, CC);

    // ---- cross-attention ----
    ln_kernel<<<NTOK, 256>>>(y,    lny_g, lny_b, p_yn);
    ln_kernel<<<NTOK, 256>>>(p_x1, ln2_g, ln2_b, p_xn);
    gemm_tc<false><<<dim3(CC / 128, NTOK / 128), 256>>>(
        p_xn, pq_w, nullptr, nullptr, p_cq, NTOK, CC, CC);
    gemm_tc<false><<<dim3(CC / 128, NTOK / 128), 256>>>(
        p_yn, pk_w, nullptr, nullptr, p_ck, NTOK, CC, CC);
    gemm_tc<false><<<dim3(CC / 128, NTOK / 128), 256>>>(
        p_yn, pv_w, nullptr, nullptr, p_cv, NTOK, CC, CC);
    simmean_kernel<<<(BB * NQ_ * NK_) / 256, 256>>>(sims);
    detect_mask_kernel<<<1, 1>>>((const unsigned char*)mask);
    attn_kernel<<<dim3(NQ_ / 64, HH, BB), 256>>>(
        p_cq, p_ck, p_cv,
        CC, CC,
        (long long)NQ_ * CC, DH_,
        (long long)NQ_ * CC, DH_,
        p_sa, sims, p_sm, mask);
    gemm_tc<false><<<dim3(CC / 128, NTOK / 128), 256>>>(
        p_sa, cproj_w, cproj_b, p_x1, p_x2, NTOK, CC, CC);

    // ---- MLP ----
    ln_kernel<<<NTOK, 256>>>(p_x2, ln3_g, ln3_b, p_xn);
    gemm_tc<true><<<dim3(HID / 128, NTOK / 128), 256>>>(
        p_xn, fc1_w, fc1_b, nullptr, p_hid, NTOK, HID, CC);
    gemm_tc<false><<<dim3(CC / 128, NTOK / 128), 256>>>(
        p_hid, fc2_w, fc2_b, p_x2, out, NTOK, CC, HID);

    // ---- y passthrough (second half of output), only if out holds (x, y) ----
    if (out_size >= 2 * NTOK * CC) {
        copy4_kernel<<<(NTOK * CC / 4 + 255) / 256, 256>>>(
            (const float4*)y, (float4*)(out + (size_t)NTOK * CC), NTOK * CC / 4);
    }
}

// round 5
// speedup vs baseline: 1.7351x; 1.1365x over previous
#include <cuda_runtime.h>
#include <math.h>
#include <stdint.h>

// ---------------------------------------------------------------------------
// Problem constants
// ---------------------------------------------------------------------------
#define BB   4
#define NQ_  1024
#define NK_  1024
#define CC   768
#define HH   12
#define DH_  64
#define NTOK (BB * NQ_)      // 4096
#define HID  3072
#define ATT_SCALE 0.125f     // 64^-0.5
#define LNEPS 1e-5f

// ---------------------------------------------------------------------------
// Scratch (device globals: allocation-free, graph-capture safe)
// ---------------------------------------------------------------------------
__device__ float g_xn     [NTOK * CC];
__device__ float g_qkv    [NTOK * 3 * CC];
__device__ float g_sa     [NTOK * CC];
__device__ float g_x1     [NTOK * CC];
__device__ float g_yn     [NTOK * CC];
__device__ float g_cq     [NTOK * CC];
__device__ float g_ck     [NTOK * CC];
__device__ float g_cv     [NTOK * CC];
__device__ float g_x2     [NTOK * CC];
__device__ float g_hid    [NTOK * HID];
__device__ float g_simmean[(size_t)BB * NQ_ * NK_];
__device__ int   g_mask_kind;   // 0 = uint8, 1 = int32, 2 = float32

// ---------------------------------------------------------------------------
// mma helpers
// ---------------------------------------------------------------------------
__device__ __forceinline__ uint32_t f2tf32(float x) {
    uint32_t u;
    asm("cvt.rna.tf32.f32 %0, %1;" : "=r"(u) : "f"(x));
    return u;
}

__device__ __forceinline__ uint32_t pack_bf16x2(float lo, float hi) {
    uint32_t r;   // PTX: cvt d, a, b -> d.hi=cvt(a), d.lo=cvt(b)
    asm("cvt.rn.bf16x2.f32 %0, %1, %2;" : "=r"(r) : "f"(hi), "f"(lo));
    return r;
}

__device__ __forceinline__ void mma_tf32(float* c, const uint32_t* a, const uint32_t* b) {
    asm volatile(
        "mma.sync.aligned.m16n8k8.row.col.f32.tf32.tf32.f32 "
        "{%0,%1,%2,%3}, {%4,%5,%6,%7}, {%8,%9}, {%0,%1,%2,%3};"
        : "+f"(c[0]), "+f"(c[1]), "+f"(c[2]), "+f"(c[3])
        : "r"(a[0]), "r"(a[1]), "r"(a[2]), "r"(a[3]), "r"(b[0]), "r"(b[1]));
}

__device__ __forceinline__ void mma_bf16(float* c, const uint32_t* a, const uint32_t* b) {
    asm volatile(
        "mma.sync.aligned.m16n8k16.row.col.f32.bf16.bf16.f32 "
        "{%0,%1,%2,%3}, {%4,%5,%6,%7}, {%8,%9}, {%0,%1,%2,%3};"
        : "+f"(c[0]), "+f"(c[1]), "+f"(c[2]), "+f"(c[3])
        : "r"(a[0]), "r"(a[1]), "r"(a[2]), "r"(a[3]), "r"(b[0]), "r"(b[1]));
}

// ---------------------------------------------------------------------------
// LayerNorm: one block per row of 768, 256 threads (3 elems/thread)
// ---------------------------------------------------------------------------
__global__ __launch_bounds__(256)
void ln_kernel(const float* __restrict__ x, const float* __restrict__ gg,
               const float* __restrict__ bb, float* __restrict__ out)
{
    __shared__ float sh[32];
    int row = blockIdx.x;
    int t = threadIdx.x;
    const float* xr = x + (size_t)row * CC;
    float a0 = xr[t], a1 = xr[t + 256], a2 = xr[t + 512];

    float s = a0 + a1 + a2;
    #pragma unroll
    for (int o = 16; o; o >>= 1) s += __shfl_xor_sync(0xffffffffu, s, o);
    if ((t & 31) == 0) sh[t >> 5] = s;
    __syncthreads();
    if (t < 32) {
        float v = (t < 8) ? sh[t] : 0.f;
        #pragma unroll
        for (int o = 4; o; o >>= 1) v += __shfl_xor_sync(0xffffffffu, v, o);
        if (t == 0) sh[0] = v;
    }
    __syncthreads();
    float mean = sh[0] * (1.0f / CC);
    __syncthreads();

    float d0 = a0 - mean, d1 = a1 - mean, d2 = a2 - mean;
    s = d0 * d0 + d1 * d1 + d2 * d2;
    #pragma unroll
    for (int o = 16; o; o >>= 1) s += __shfl_xor_sync(0xffffffffu, s, o);
    if ((t & 31) == 0) sh[t >> 5] = s;
    __syncthreads();
    if (t < 32) {
        float v = (t < 8) ? sh[t] : 0.f;
        #pragma unroll
        for (int o = 4; o; o >>= 1) v += __shfl_xor_sync(0xffffffffu, v, o);
        if (t == 0) sh[0] = v;
    }
    __syncthreads();
    float rstd = rsqrtf(sh[0] * (1.0f / CC) + LNEPS);

    float* orow = out + (size_t)row * CC;
    orow[t]       = d0 * rstd * gg[t]       + bb[t];
    orow[t + 256] = d1 * rstd * gg[t + 256] + bb[t + 256];
    orow[t + 512] = d2 * rstd * gg[t + 512] + bb[t + 512];
}

// ---------------------------------------------------------------------------
// Tensor-core NT GEMM v2 (tf32): C = A[M,K] @ W[N,K]^T (+bias)(+GELU)(+res)
// BM=BN=128, BK=16, 128 threads / 4 warps (2x2), warp tile 64x64,
// double-buffered smem. M%128==0, N%128==0, K%16==0.
// ---------------------------------------------------------------------------
template<bool GELU>
__global__ __launch_bounds__(128)
void gemm_tc2(const float* __restrict__ A, const float* __restrict__ W,
              const float* __restrict__ bias, const float* __restrict__ res,
              float* __restrict__ Cout, int M, int N, int K)
{
    __shared__ uint32_t As[2][128][20];   // [stage][m][k] tf32 (+4 pad)
    __shared__ uint32_t Bs[2][128][20];   // [stage][n][k]

    int t = threadIdx.x;
    int lane = t & 31, wid = t >> 5;
    int warp_m = wid >> 1, warp_n = wid & 1;
    int g = lane >> 2, c = lane & 3;
    int m0 = blockIdx.y * 128, n0 = blockIdx.x * 128;

    const float4* Ap = (const float4*)(A + (size_t)(m0 + t) * K);
    const float4* Wp = (const float4*)(W + (size_t)(n0 + t) * K);

    float acc[4][8][4];
    #pragma unroll
    for (int i = 0; i < 4; i++)
        #pragma unroll
        for (int j = 0; j < 8; j++)
            #pragma unroll
            for (int r = 0; r < 4; r++) acc[i][j][r] = 0.f;

    float4 ar[4], br[4];
    #pragma unroll
    for (int j = 0; j < 4; j++) { ar[j] = Ap[j]; br[j] = Wp[j]; }
    #pragma unroll
    for (int j = 0; j < 4; j++) {
        As[0][t][j*4+0] = f2tf32(ar[j].x); As[0][t][j*4+1] = f2tf32(ar[j].y);
        As[0][t][j*4+2] = f2tf32(ar[j].z); As[0][t][j*4+3] = f2tf32(ar[j].w);
        Bs[0][t][j*4+0] = f2tf32(br[j].x); Bs[0][t][j*4+1] = f2tf32(br[j].y);
        Bs[0][t][j*4+2] = f2tf32(br[j].z); Bs[0][t][j*4+3] = f2tf32(br[j].w);
    }
    __syncthreads();

    int nkt = K >> 4;
    for (int kt = 0; kt < nkt; kt++) {
        int cur = kt & 1;
        if (kt + 1 < nkt) {
            int base = (kt + 1) * 4;
            #pragma unroll
            for (int j = 0; j < 4; j++) { ar[j] = Ap[base + j]; br[j] = Wp[base + j]; }
        }
        #pragma unroll
        for (int k8 = 0; k8 < 16; k8 += 8) {
            int c0 = k8 + c;
            uint32_t bf[8][2];
            #pragma unroll
            for (int nt = 0; nt < 8; nt++) {
                int n = warp_n * 64 + nt * 8 + g;
                bf[nt][0] = Bs[cur][n][c0]; bf[nt][1] = Bs[cur][n][c0 + 4];
            }
            #pragma unroll
            for (int mt = 0; mt < 4; mt++) {
                int r = warp_m * 64 + mt * 16 + g;
                uint32_t af[4] = {As[cur][r][c0], As[cur][r + 8][c0],
                                  As[cur][r][c0 + 4], As[cur][r + 8][c0 + 4]};
                #pragma unroll
                for (int nt = 0; nt < 8; nt++)
                    mma_tf32(acc[mt][nt], af, bf[nt]);
            }
        }
        if (kt + 1 < nkt) {
            int nxt = 1 - cur;
            #pragma unroll
            for (int j = 0; j < 4; j++) {
                As[nxt][t][j*4+0] = f2tf32(ar[j].x); As[nxt][t][j*4+1] = f2tf32(ar[j].y);
                As[nxt][t][j*4+2] = f2tf32(ar[j].z); As[nxt][t][j*4+3] = f2tf32(ar[j].w);
                Bs[nxt][t][j*4+0] = f2tf32(br[j].x); Bs[nxt][t][j*4+1] = f2tf32(br[j].y);
                Bs[nxt][t][j*4+2] = f2tf32(br[j].z); Bs[nxt][t][j*4+3] = f2tf32(br[j].w);
            }
        }
        __syncthreads();
    }

    // epilogue
    #pragma unroll
    for (int mt = 0; mt < 4; mt++) {
        int row0 = m0 + warp_m * 64 + mt * 16 + g;
        #pragma unroll
        for (int nt = 0; nt < 8; nt++) {
            int col = n0 + warp_n * 64 + nt * 8 + c * 2;
            float b0 = bias ? bias[col]     : 0.f;
            float b1 = bias ? bias[col + 1] : 0.f;

            float v00 = acc[mt][nt][0] + b0, v01 = acc[mt][nt][1] + b1;
            float v10 = acc[mt][nt][2] + b0, v11 = acc[mt][nt][3] + b1;
            if (GELU) {
                v00 = 0.5f * v00 * (1.0f + erff(v00 * 0.70710678118654752f));
                v01 = 0.5f * v01 * (1.0f + erff(v01 * 0.70710678118654752f));
                v10 = 0.5f * v10 * (1.0f + erff(v10 * 0.70710678118654752f));
                v11 = 0.5f * v11 * (1.0f + erff(v11 * 0.70710678118654752f));
            }
            if (res) {
                v00 += res[(size_t)row0 * N + col];
                v01 += res[(size_t)row0 * N + col + 1];
                v10 += res[(size_t)(row0 + 8) * N + col];
                v11 += res[(size_t)(row0 + 8) * N + col + 1];
            }
            *(float2*)&Cout[(size_t)row0 * N + col]       = make_float2(v00, v01);
            *(float2*)&Cout[(size_t)(row0 + 8) * N + col] = make_float2(v10, v11);
        }
    }
}

// ---------------------------------------------------------------------------
// Tensor-core flash attention. Block = 64 q-rows, 4 warps (16 q-rows each),
// kv tiles of 64, DH=64. S = QK^T in tf32 mma; softmax in C-fragment regs
// (quad shfl reductions); P stays in regs as bf16 A-fragment; PV in bf16 mma.
// Cross-attention adds (sims - simmean) bias + mask.
// ---------------------------------------------------------------------------
template<bool CROSS>
__global__ __launch_bounds__(128)
void attn_tc(const float* __restrict__ Qb, const float* __restrict__ Kb,
             const float* __restrict__ Vb,
             int q_rs, int kv_rs,
             long long q_bs, long long q_ho, long long kv_bs, long long kv_ho,
             float* __restrict__ Ob,
             const float* __restrict__ sims, const float* __restrict__ simmean,
             const void* __restrict__ maskp)
{
    __shared__ uint32_t Qs[64][68];   // tf32 [q][d]
    __shared__ uint32_t Ks[64][68];   // tf32 [kv][d]
    __shared__ uint32_t Vp[64][36];   // bf16x2 [d][kv-pair]

    int t = threadIdx.x;
    int lane = t & 31, wid = t >> 5;
    int g = lane >> 2, c = lane & 3;
    int b = blockIdx.z, h = blockIdx.y;
    int q0 = blockIdx.x * 64;

    const float* Qp = Qb + (long long)b * q_bs  + (long long)h * q_ho;
    const float* Kp = Kb + (long long)b * kv_bs + (long long)h * kv_ho;
    const float* Vg = Vb + (long long)b * kv_bs + (long long)h * kv_ho;

    for (int idx = t; idx < 4096; idx += 128) {
        int r = idx >> 6, d = idx & 63;
        Qs[r][d] = f2tf32(Qp[(size_t)(q0 + r) * q_rs + d]);
    }
    __syncthreads();

    // cache Q fragments for this warp's 16 rows
    uint32_t qf[8][4];
    {
        int r = wid * 16 + g;
        #pragma unroll
        for (int k8 = 0; k8 < 8; k8++) {
            int c0 = k8 * 8 + c;
            qf[k8][0] = Qs[r][c0];     qf[k8][1] = Qs[r + 8][c0];
            qf[k8][2] = Qs[r][c0 + 4]; qf[k8][3] = Qs[r + 8][c0 + 4];
        }
    }

    float oacc[8][4];
    #pragma unroll
    for (int i = 0; i < 8; i++)
        #pragma unroll
        for (int j = 0; j < 4; j++) oacc[i][j] = 0.f;

    float rm0 = -1e30f, rm1 = -1e30f, rl0 = 0.f, rl1 = 0.f;
    int r0 = q0 + wid * 16 + g;   // rows for c-regs {0,1}
    int r1 = r0 + 8;              // rows for c-regs {2,3}
    const int mkind = CROSS ? g_mask_kind : 0;

    for (int kv0 = 0; kv0 < NK_; kv0 += 64) {
        __syncthreads();   // previous tile's smem reads done
        for (int idx = t; idx < 4096; idx += 128) {
            int r = idx >> 6, d = idx & 63;
            Ks[r][d] = f2tf32(Kp[(size_t)(kv0 + r) * kv_rs + d]);
        }
        for (int idx = t; idx < 2048; idx += 128) {
            int d = idx & 63, j = idx >> 6;
            float v0 = Vg[(size_t)(kv0 + 2 * j)     * kv_rs + d];
            float v1 = Vg[(size_t)(kv0 + 2 * j + 1) * kv_rs + d];
            Vp[d][j] = pack_bf16x2(v0, v1);
        }
        __syncthreads();

        // ---- S = Q K^T ----
        float sacc[8][4];
        #pragma unroll
        for (int i = 0; i < 8; i++)
            #pragma unroll
            for (int j = 0; j < 4; j++) sacc[i][j] = 0.f;
        #pragma unroll
        for (int k8 = 0; k8 < 8; k8++) {
            int c0 = k8 * 8 + c;
            #pragma unroll
            for (int nt = 0; nt < 8; nt++) {
                int n = nt * 8 + g;
                uint32_t bf[2] = {Ks[n][c0], Ks[n][c0 + 4]};
                mma_tf32(sacc[nt], qf[k8], bf);
            }
        }

        // ---- scale (+bias, mask) ----
        #pragma unroll
        for (int nt = 0; nt < 8; nt++) {
            int col = kv0 + nt * 8 + 2 * c;
            float s0 = sacc[nt][0] * ATT_SCALE, s1 = sacc[nt][1] * ATT_SCALE;
            float s2 = sacc[nt][2] * ATT_SCALE, s3 = sacc[nt][3] * ATT_SCALE;
            if (CROSS) {
                size_t base = (size_t)(b * HH + h) * NQ_;
                float2 sv0 = *(const float2*)(sims + (base + r0) * NK_ + col);
                float2 sv1 = *(const float2*)(sims + (base + r1) * NK_ + col);
                float2 mm0 = *(const float2*)(simmean + ((size_t)b * NQ_ + r0) * NK_ + col);
                float2 mm1 = *(const float2*)(simmean + ((size_t)b * NQ_ + r1) * NK_ + col);
                s0 += sv0.x - mm0.x; s1 += sv0.y - mm0.y;
                s2 += sv1.x - mm1.x; s3 += sv1.y - mm1.y;
                size_t mi0 = (size_t)r0 * NK_ + col, mi1 = (size_t)r1 * NK_ + col;
                bool k0a, k0b, k1a, k1b;
                if (mkind == 0) {
                    const unsigned char* m = (const unsigned char*)maskp;
                    k0a = m[mi0] != 0; k0b = m[mi0 + 1] != 0;
                    k1a = m[mi1] != 0; k1b = m[mi1 + 1] != 0;
                } else if (mkind == 1) {
                    const int* m = (const int*)maskp;
                    k0a = m[mi0] != 0; k0b = m[mi0 + 1] != 0;
                    k1a = m[mi1] != 0; k1b = m[mi1 + 1] != 0;
                } else {
                    const float* m = (const float*)maskp;
                    k0a = m[mi0] != 0.f; k0b = m[mi0 + 1] != 0.f;
                    k1a = m[mi1] != 0.f; k1b = m[mi1 + 1] != 0.f;
                }
                if (!k0a) s0 = -1e30f;
                if (!k0b) s1 = -1e30f;
                if (!k1a) s2 = -1e30f;
                if (!k1b) s3 = -1e30f;
            }
            sacc[nt][0] = s0; sacc[nt][1] = s1; sacc[nt][2] = s2; sacc[nt][3] = s3;
        }

        // ---- online softmax (rows r0, r1; reduce over quad lanes) ----
        float tm0 = -1e30f, tm1 = -1e30f;
        #pragma unroll
        for (int nt = 0; nt < 8; nt++) {
            tm0 = fmaxf(tm0, fmaxf(sacc[nt][0], sacc[nt][1]));
            tm1 = fmaxf(tm1, fmaxf(sacc[nt][2], sacc[nt][3]));
        }
        tm0 = fmaxf(tm0, __shfl_xor_sync(0xffffffffu, tm0, 1));
        tm0 = fmaxf(tm0, __shfl_xor_sync(0xffffffffu, tm0, 2));
        tm1 = fmaxf(tm1, __shfl_xor_sync(0xffffffffu, tm1, 1));
        tm1 = fmaxf(tm1, __shfl_xor_sync(0xffffffffu, tm1, 2));
        float nm0 = fmaxf(rm0, tm0), nm1 = fmaxf(rm1, tm1);
        float al0 = __expf(rm0 - nm0), al1 = __expf(rm1 - nm1);
        float sum0 = 0.f, sum1 = 0.f;
        #pragma unroll
        for (int nt = 0; nt < 8; nt++) {
            float p0 = __expf(sacc[nt][0] - nm0);
            float p1 = __expf(sacc[nt][1] - nm0);
            float p2 = __expf(sacc[nt][2] - nm1);
            float p3 = __expf(sacc[nt][3] - nm1);
            sum0 += p0 + p1; sum1 += p2 + p3;
            sacc[nt][0] = p0; sacc[nt][1] = p1; sacc[nt][2] = p2; sacc[nt][3] = p3;
        }
        sum0 += __shfl_xor_sync(0xffffffffu, sum0, 1);
        sum0 += __shfl_xor_sync(0xffffffffu, sum0, 2);
        sum1 += __shfl_xor_sync(0xffffffffu, sum1, 1);
        sum1 += __shfl_xor_sync(0xffffffffu, sum1, 2);
        rl0 = rl0 * al0 + sum0; rl1 = rl1 * al1 + sum1;
        rm0 = nm0; rm1 = nm1;
        #pragma unroll
        for (int i = 0; i < 8; i++) {
            oacc[i][0] *= al0; oacc[i][1] *= al0;
            oacc[i][2] *= al1; oacc[i][3] *= al1;
        }

        // ---- pack P (C-layout == A-layout of m16n8k16) ----
        uint32_t pa[4][4];
        #pragma unroll
        for (int j = 0; j < 4; j++) {
            pa[j][0] = pack_bf16x2(sacc[2*j][0],     sacc[2*j][1]);
            pa[j][1] = pack_bf16x2(sacc[2*j][2],     sacc[2*j][3]);
            pa[j][2] = pack_bf16x2(sacc[2*j + 1][0], sacc[2*j + 1][1]);
            pa[j][3] = pack_bf16x2(sacc[2*j + 1][2], sacc[2*j + 1][3]);
        }

        // ---- O += P V ----
        #pragma unroll
        for (int ntd = 0; ntd < 8; ntd++) {
            int n = ntd * 8 + g;
            #pragma unroll
            for (int j = 0; j < 4; j++) {
                uint32_t bb[2] = {Vp[n][j * 8 + c], Vp[n][j * 8 + c + 4]};
                mma_bf16(oacc[ntd], pa[j], bb);
            }
        }
    }

    float inv0 = 1.f / rl0, inv1 = 1.f / rl1;
    #pragma unroll
    for (int ntd = 0; ntd < 8; ntd++) {
        int col = ntd * 8 + 2 * c;
        float* op0 = Ob + ((size_t)b * NQ_ + r0) * CC + h * DH_ + col;
        float* op1 = Ob + ((size_t)b * NQ_ + r1) * CC + h * DH_ + col;
        *(float2*)op0 = make_float2(oacc[ntd][0] * inv0, oacc[ntd][1] * inv0);
        *(float2*)op1 = make_float2(oacc[ntd][2] * inv1, oacc[ntd][3] * inv1);
    }
}

// ---------------------------------------------------------------------------
// similarities head-mean: g_simmean[b,q,k] = mean_h sims[b,h,q,k]
// ---------------------------------------------------------------------------
__global__ __launch_bounds__(256)
void simmean_kernel(const float* __restrict__ sims)
{
    size_t idx = (size_t)blockIdx.x * 256 + threadIdx.x;
    int b = (int)(idx >> 20);
    size_t qk = idx & 1048575u;
    float s = 0.f;
    #pragma unroll
    for (int h = 0; h < HH; h++)
        s += sims[(((size_t)(b * HH + h)) << 20) + qk];
    g_simmean[idx] = s * (1.0f / HH);
}

// ---------------------------------------------------------------------------
// Mask dtype detection (u8 vs i32 vs f32 storage of bool). Deterministic.
// ---------------------------------------------------------------------------
__global__ void detect_mask_kernel(const unsigned char* __restrict__ m)
{
    if (threadIdx.x == 0 && blockIdx.x == 0) {
        int ones = 0, nonbin = 0;
        for (int i = 0; i < 4096; i++) {
            unsigned char v = m[i];
            if (v > 1) nonbin = 1;
            if (v == 1) ones++;
        }
        g_mask_kind = nonbin ? 2 : (ones > 1228 ? 0 : 1);
    }
}

// ---------------------------------------------------------------------------
// float4 copy (y passthrough into second half of output)
// ---------------------------------------------------------------------------
__global__ __launch_bounds__(256)
void copy4_kernel(const float4* __restrict__ s, float4* __restrict__ d, int n4)
{
    int i = blockIdx.x * 256 + threadIdx.x;
    if (i < n4) d[i] = s[i];
}

// ---------------------------------------------------------------------------
// Launch
// ---------------------------------------------------------------------------
extern "C" void kernel_launch(void* const* d_in, const int* in_sizes, int n_in,
                              void* d_out, int out_size)
{
    const float* x       = (const float*)d_in[0];
    const float* y       = (const float*)d_in[1];
    const void*  mask    = d_in[4];
    const float* sims    = (const float*)d_in[5];
    const float* ln1_g   = (const float*)d_in[6];
    const float* ln1_b   = (const float*)d_in[7];
    const float* ln2_g   = (const float*)d_in[8];
    const float* ln2_b   = (const float*)d_in[9];
    const float* ln3_g   = (const float*)d_in[10];
    const float* ln3_b   = (const float*)d_in[11];
    const float* lny_g   = (const float*)d_in[12];
    const float* lny_b   = (const float*)d_in[13];
    const float* qkv_w   = (const float*)d_in[14];
    const float* aproj_w = (const float*)d_in[15];
    const float* aproj_b = (const float*)d_in[16];
    const float* pq_w    = (const float*)d_in[17];
    const float* pk_w    = (const float*)d_in[18];
    const float* pv_w    = (const float*)d_in[19];
    const float* cproj_w = (const float*)d_in[20];
    const float* cproj_b = (const float*)d_in[21];
    const float* fc1_w   = (const float*)d_in[22];
    const float* fc1_b   = (const float*)d_in[23];
    const float* fc2_w   = (const float*)d_in[24];
    const float* fc2_b   = (const float*)d_in[25];
    float* out = (float*)d_out;

    float *p_xn, *p_qkv, *p_sa, *p_x1, *p_yn, *p_cq, *p_ck, *p_cv, *p_x2, *p_hid, *p_sm;
    cudaGetSymbolAddress((void**)&p_xn,  g_xn);
    cudaGetSymbolAddress((void**)&p_qkv, g_qkv);
    cudaGetSymbolAddress((void**)&p_sa,  g_sa);
    cudaGetSymbolAddress((void**)&p_x1,  g_x1);
    cudaGetSymbolAddress((void**)&p_yn,  g_yn);
    cudaGetSymbolAddress((void**)&p_cq,  g_cq);
    cudaGetSymbolAddress((void**)&p_ck,  g_ck);
    cudaGetSymbolAddress((void**)&p_cv,  g_cv);
    cudaGetSymbolAddress((void**)&p_x2,  g_x2);
    cudaGetSymbolAddress((void**)&p_hid, g_hid);
    cudaGetSymbolAddress((void**)&p_sm,  g_simmean);

    // ---- self-attention ----
    ln_kernel<<<NTOK, 256>>>(x, ln1_g, ln1_b, p_xn);
    gemm_tc2<false><<<dim3(3 * CC / 128, NTOK / 128), 128>>>(
        p_xn, qkv_w, nullptr, nullptr, p_qkv, NTOK, 3 * CC, CC);
    attn_tc<false><<<dim3(NQ_ / 64, HH, BB), 128>>>(
        p_qkv, p_qkv + CC, p_qkv + 2 * CC,
        3 * CC, 3 * CC,
        (long long)NQ_ * 3 * CC, DH_,
        (long long)NQ_ * 3 * CC, DH_,
        p_sa, nullptr, nullptr, nullptr);
    gemm_tc2<false><<<dim3(CC / 128, NTOK / 128), 128>>>(
        p_sa, aproj_w, aproj_b, x, p_x1, NTOK, CC, CC);

    // ---- cross-attention ----
    ln_kernel<<<NTOK, 256>>>(y,    lny_g, lny_b, p_yn);
    ln_kernel<<<NTOK, 256>>>(p_x1, ln2_g, ln2_b, p_xn);
    gemm_tc2<false><<<dim3(CC / 128, NTOK / 128), 128>>>(
        p_xn, pq_w, nullptr, nullptr, p_cq, NTOK, CC, CC);
    gemm_tc2<false><<<dim3(CC / 128, NTOK / 128), 128>>>(
        p_yn, pk_w, nullptr, nullptr, p_ck, NTOK, CC, CC);
    gemm_tc2<false><<<dim3(CC / 128, NTOK / 128), 128>>>(
        p_yn, pv_w, nullptr, nullptr, p_cv, NTOK, CC, CC);
    simmean_kernel<<<(BB * NQ_ * NK_) / 256, 256>>>(sims);
    detect_mask_kernel<<<1, 1>>>((const unsigned char*)mask);
    attn_tc<true><<<dim3(NQ_ / 64, HH, BB), 128>>>(
        p_cq, p_ck, p_cv,
        CC, CC,
        (long long)NQ_ * CC, DH_,
        (long long)NQ_ * CC, DH_,
        p_sa, sims, p_sm, mask);
    gemm_tc2<false><<<dim3(CC / 128, NTOK / 128), 128>>>(
        p_sa, cproj_w, cproj_b, p_x1, p_x2, NTOK, CC, CC);

    // ---- MLP ----
    ln_kernel<<<NTOK, 256>>>(p_x2, ln3_g, ln3_b, p_xn);
    gemm_tc2<true><<<dim3(HID / 128, NTOK / 128), 128>>>(
        p_xn, fc1_w, fc1_b, nullptr, p_hid, NTOK, HID, CC);
    gemm_tc2<false><<<dim3(CC / 128, NTOK / 128), 128>>>(
        p_hid, fc2_w, fc2_b, p_x2, out, NTOK, CC, HID);

    // ---- y passthrough (second half of output), only if out holds (x, y) ----
    if (out_size >= 2 * NTOK * CC) {
        copy4_kernel<<<(NTOK * CC / 4 + 255) / 256, 256>>>(
            (const float4*)y, (float4*)(out + (size_t)NTOK * CC), NTOK * CC / 4);
    }
}

// round 6
// speedup vs baseline: 2.0520x; 1.1826x over previous
#include <cuda_runtime.h>
#include <math.h>
#include <stdint.h>

// ---------------------------------------------------------------------------
// Problem constants
// ---------------------------------------------------------------------------
#define BB   4
#define NQ_  1024
#define NK_  1024
#define CC   768
#define HH   12
#define DH_  64
#define NTOK (BB * NQ_)      // 4096
#define HID  3072
#define ATT_SCALE 0.125f     // 64^-0.5
#define LNEPS 1e-5f

// ---------------------------------------------------------------------------
// Scratch (device globals: allocation-free, graph-capture safe)
// ---------------------------------------------------------------------------
__device__ float g_xn     [NTOK * CC];
__device__ float g_qkv    [NTOK * 3 * CC];
__device__ float g_sa     [NTOK * CC];
__device__ float g_x1     [NTOK * CC];
__device__ float g_yn     [NTOK * CC];
__device__ float g_cq     [NTOK * CC];
__device__ float g_ck     [NTOK * CC];
__device__ float g_cv     [NTOK * CC];
__device__ float g_x2     [NTOK * CC];
__device__ float g_hid    [NTOK * HID];
__device__ float g_simmean[(size_t)BB * NQ_ * NK_];
__device__ int   g_mask_kind;   // 0 = uint8, 1 = int32, 2 = float32

// ---------------------------------------------------------------------------
// mma / async helpers
// ---------------------------------------------------------------------------
__device__ __forceinline__ uint32_t f2tf32(float x) {
    uint32_t u;
    asm("cvt.rna.tf32.f32 %0, %1;" : "=r"(u) : "f"(x));
    return u;
}

__device__ __forceinline__ uint32_t pack_bf16x2(float lo, float hi) {
    uint32_t r;   // PTX: cvt d, a, b -> d.hi=cvt(a), d.lo=cvt(b)
    asm("cvt.rn.bf16x2.f32 %0, %1, %2;" : "=r"(r) : "f"(hi), "f"(lo));
    return r;
}

__device__ __forceinline__ void mma_tf32(float* c, const uint32_t* a, const uint32_t* b) {
    asm volatile(
        "mma.sync.aligned.m16n8k8.row.col.f32.tf32.tf32.f32 "
        "{%0,%1,%2,%3}, {%4,%5,%6,%7}, {%8,%9}, {%0,%1,%2,%3};"
        : "+f"(c[0]), "+f"(c[1]), "+f"(c[2]), "+f"(c[3])
        : "r"(a[0]), "r"(a[1]), "r"(a[2]), "r"(a[3]), "r"(b[0]), "r"(b[1]));
}

__device__ __forceinline__ void mma_bf16(float* c, const uint32_t* a, const uint32_t* b) {
    asm volatile(
        "mma.sync.aligned.m16n8k16.row.col.f32.bf16.bf16.f32 "
        "{%0,%1,%2,%3}, {%4,%5,%6,%7}, {%8,%9}, {%0,%1,%2,%3};"
        : "+f"(c[0]), "+f"(c[1]), "+f"(c[2]), "+f"(c[3])
        : "r"(a[0]), "r"(a[1]), "r"(a[2]), "r"(a[3]), "r"(b[0]), "r"(b[1]));
}

__device__ __forceinline__ void ldsm_x4(uint32_t& r0, uint32_t& r1,
                                        uint32_t& r2, uint32_t& r3, uint32_t addr) {
    asm volatile("ldmatrix.sync.aligned.m8n8.x4.shared.b16 {%0,%1,%2,%3}, [%4];"
                 : "=r"(r0), "=r"(r1), "=r"(r2), "=r"(r3) : "r"(addr));
}

#define CP16(dst, src) \
    asm volatile("cp.async.cg.shared.global [%0], [%1], 16;" :: "r"(dst), "l"(src))
#define CP_COMMIT() asm volatile("cp.async.commit_group;")
#define CP_WAIT(n)  asm volatile("cp.async.wait_group %0;" :: "n"(n))

// ---------------------------------------------------------------------------
// LayerNorm: one block per row of 768, 256 threads (3 elems/thread)
// ---------------------------------------------------------------------------
__global__ __launch_bounds__(256)
void ln_kernel(const float* __restrict__ x, const float* __restrict__ gg,
               const float* __restrict__ bb, float* __restrict__ out)
{
    __shared__ float sh[32];
    int row = blockIdx.x;
    int t = threadIdx.x;
    const float* xr = x + (size_t)row * CC;
    float a0 = xr[t], a1 = xr[t + 256], a2 = xr[t + 512];

    float s = a0 + a1 + a2;
    #pragma unroll
    for (int o = 16; o; o >>= 1) s += __shfl_xor_sync(0xffffffffu, s, o);
    if ((t & 31) == 0) sh[t >> 5] = s;
    __syncthreads();
    if (t < 32) {
        float v = (t < 8) ? sh[t] : 0.f;
        #pragma unroll
        for (int o = 4; o; o >>= 1) v += __shfl_xor_sync(0xffffffffu, v, o);
        if (t == 0) sh[0] = v;
    }
    __syncthreads();
    float mean = sh[0] * (1.0f / CC);
    __syncthreads();

    float d0 = a0 - mean, d1 = a1 - mean, d2 = a2 - mean;
    s = d0 * d0 + d1 * d1 + d2 * d2;
    #pragma unroll
    for (int o = 16; o; o >>= 1) s += __shfl_xor_sync(0xffffffffu, s, o);
    if ((t & 31) == 0) sh[t >> 5] = s;
    __syncthreads();
    if (t < 32) {
        float v = (t < 8) ? sh[t] : 0.f;
        #pragma unroll
        for (int o = 4; o; o >>= 1) v += __shfl_xor_sync(0xffffffffu, v, o);
        if (t == 0) sh[0] = v;
    }
    __syncthreads();
    float rstd = rsqrtf(sh[0] * (1.0f / CC) + LNEPS);

    float* orow = out + (size_t)row * CC;
    orow[t]       = d0 * rstd * gg[t]       + bb[t];
    orow[t + 256] = d1 * rstd * gg[t + 256] + bb[t + 256];
    orow[t + 512] = d2 * rstd * gg[t + 512] + bb[t + 512];
}

// ---------------------------------------------------------------------------
// Tensor-core NT GEMM v3 (tf32): C = A[M,K] @ W[N,K]^T (+bias)(+GELU)(+res)
// BM=BN=128, BK=16, 256 threads / 8 warps (2x4), warp tile 64x32.
// cp.async double-buffered smem; ldmatrix fragment loads; raw fp32 bits fed
// to tf32 mma (hardware truncation). M%128==0, N%128==0, K%16==0.
// ---------------------------------------------------------------------------
#define GSTAGE 10240   // 128 rows * 20 words * 4 B per stage

template<bool GELU>
__global__ __launch_bounds__(256, 2)
void gemm_tc3(const float* __restrict__ A, const float* __restrict__ W,
              const float* __restrict__ bias, const float* __restrict__ res,
              float* __restrict__ Cout, int M, int N, int K)
{
    __shared__ float As[2][128][20];
    __shared__ float Bs[2][128][20];

    int t = threadIdx.x;
    int lane = t & 31, wid = t >> 5;
    int warp_m = wid >> 2;            // 0..1
    int warp_n = wid & 3;             // 0..3
    int g = lane >> 2, c = lane & 3;
    int m0 = blockIdx.y * 128, n0 = blockIdx.x * 128;

    uint32_t smemA = (uint32_t)__cvta_generic_to_shared(&As[0][0][0]);
    uint32_t smemB = (uint32_t)__cvta_generic_to_shared(&Bs[0][0][0]);

    // ldmatrix lane addressing
    int mi = lane >> 3, l7 = lane & 7;
    int rowA = warp_m * 64 + (mi & 1) * 8 + l7;
    int colA = (mi >> 1) * 4;
    uint32_t baseA = smemA + (uint32_t)(rowA * 20 + colA) * 4;
    int rowB = warp_n * 32 + (mi >> 1) * 8 + l7;
    int colB = (mi & 1) * 4;
    uint32_t baseB = smemB + (uint32_t)(rowB * 20 + colB) * 4;

    // cp.async addressing: thread t loads 2x16B per matrix
    int ldrow = t >> 1;
    int c4    = (t & 1) * 2;          // float4 index 0..3 (two per thread)
    const float* Asrc0 = A + (size_t)(m0 + ldrow) * K + c4 * 4;
    const float* Wsrc0 = W + (size_t)(n0 + ldrow) * K + c4 * 4;
    uint32_t dstA = smemA + (uint32_t)(ldrow * 20 + c4 * 4) * 4;
    uint32_t dstB = smemB + (uint32_t)(ldrow * 20 + c4 * 4) * 4;

    float acc[4][4][4];
    #pragma unroll
    for (int i = 0; i < 4; i++)
        #pragma unroll
        for (int j = 0; j < 4; j++)
            #pragma unroll
            for (int r = 0; r < 4; r++) acc[i][j][r] = 0.f;

    // prologue: stage 0
    CP16(dstA,      Asrc0);
    CP16(dstA + 16, Asrc0 + 4);
    CP16(dstB,      Wsrc0);
    CP16(dstB + 16, Wsrc0 + 4);
    CP_COMMIT();

    int nkt = K >> 4;
    for (int kt = 0; kt < nkt; kt++) {
        int cur = kt & 1;
        if (kt + 1 < nkt) {
            int nxt = 1 - cur;
            const float* as = Asrc0 + (kt + 1) * 16;
            const float* ws = Wsrc0 + (kt + 1) * 16;
            uint32_t da = dstA + nxt * GSTAGE;
            uint32_t db = dstB + nxt * GSTAGE;
            CP16(da,      as);
            CP16(da + 16, as + 4);
            CP16(db,      ws);
            CP16(db + 16, ws + 4);
            CP_COMMIT();
            CP_WAIT(1);
        } else {
            CP_WAIT(0);
        }
        __syncthreads();

        #pragma unroll
        for (int k8 = 0; k8 < 2; k8++) {
            uint32_t af[4][4], bf[4][2];
            #pragma unroll
            for (int mt = 0; mt < 4; mt++)
                ldsm_x4(af[mt][0], af[mt][1], af[mt][2], af[mt][3],
                        baseA + cur * GSTAGE + mt * (16 * 80) + k8 * 32);
            #pragma unroll
            for (int j = 0; j < 2; j++)
                ldsm_x4(bf[2*j][0], bf[2*j][1], bf[2*j+1][0], bf[2*j+1][1],
                        baseB + cur * GSTAGE + j * (16 * 80) + k8 * 32);
            #pragma unroll
            for (int mt = 0; mt < 4; mt++)
                #pragma unroll
                for (int nt = 0; nt < 4; nt++)
                    mma_tf32(acc[mt][nt], af[mt], bf[nt]);
        }
        __syncthreads();
    }

    // epilogue
    #pragma unroll
    for (int mt = 0; mt < 4; mt++) {
        int row0 = m0 + warp_m * 64 + mt * 16 + g;
        #pragma unroll
        for (int nt = 0; nt < 4; nt++) {
            int col = n0 + warp_n * 32 + nt * 8 + c * 2;
            float b0 = bias ? bias[col]     : 0.f;
            float b1 = bias ? bias[col + 1] : 0.f;

            float v00 = acc[mt][nt][0] + b0, v01 = acc[mt][nt][1] + b1;
            float v10 = acc[mt][nt][2] + b0, v11 = acc[mt][nt][3] + b1;
            if (GELU) {
                v00 = 0.5f * v00 * (1.0f + erff(v00 * 0.70710678118654752f));
                v01 = 0.5f * v01 * (1.0f + erff(v01 * 0.70710678118654752f));
                v10 = 0.5f * v10 * (1.0f + erff(v10 * 0.70710678118654752f));
                v11 = 0.5f * v11 * (1.0f + erff(v11 * 0.70710678118654752f));
            }
            if (res) {
                v00 += res[(size_t)row0 * N + col];
                v01 += res[(size_t)row0 * N + col + 1];
                v10 += res[(size_t)(row0 + 8) * N + col];
                v11 += res[(size_t)(row0 + 8) * N + col + 1];
            }
            *(float2*)&Cout[(size_t)row0 * N + col]       = make_float2(v00, v01);
            *(float2*)&Cout[(size_t)(row0 + 8) * N + col] = make_float2(v10, v11);
        }
    }
}

// ---------------------------------------------------------------------------
// Tensor-core flash attention. Block = 64 q-rows, 4 warps (16 q-rows each),
// kv tiles of 64, DH=64. S = QK^T in tf32 mma; softmax in C-fragment regs;
// P stays in regs as bf16 A-fragment; PV in bf16 mma.
// ---------------------------------------------------------------------------
template<bool CROSS>
__global__ __launch_bounds__(128)
void attn_tc(const float* __restrict__ Qb, const float* __restrict__ Kb,
             const float* __restrict__ Vb,
             int q_rs, int kv_rs,
             long long q_bs, long long q_ho, long long kv_bs, long long kv_ho,
             float* __restrict__ Ob,
             const float* __restrict__ sims, const float* __restrict__ simmean,
             const void* __restrict__ maskp)
{
    __shared__ uint32_t Qs[64][68];   // tf32 [q][d]
    __shared__ uint32_t Ks[64][68];   // tf32 [kv][d]
    __shared__ uint32_t Vp[64][36];   // bf16x2 [d][kv-pair]

    int t = threadIdx.x;
    int lane = t & 31, wid = t >> 5;
    int g = lane >> 2, c = lane & 3;
    int b = blockIdx.z, h = blockIdx.y;
    int q0 = blockIdx.x * 64;

    const float* Qp = Qb + (long long)b * q_bs  + (long long)h * q_ho;
    const float* Kp = Kb + (long long)b * kv_bs + (long long)h * kv_ho;
    const float* Vg = Vb + (long long)b * kv_bs + (long long)h * kv_ho;

    for (int idx = t; idx < 4096; idx += 128) {
        int r = idx >> 6, d = idx & 63;
        Qs[r][d] = f2tf32(Qp[(size_t)(q0 + r) * q_rs + d]);
    }
    __syncthreads();

    uint32_t qf[8][4];
    {
        int r = wid * 16 + g;
        #pragma unroll
        for (int k8 = 0; k8 < 8; k8++) {
            int c0 = k8 * 8 + c;
            qf[k8][0] = Qs[r][c0];     qf[k8][1] = Qs[r + 8][c0];
            qf[k8][2] = Qs[r][c0 + 4]; qf[k8][3] = Qs[r + 8][c0 + 4];
        }
    }

    float oacc[8][4];
    #pragma unroll
    for (int i = 0; i < 8; i++)
        #pragma unroll
        for (int j = 0; j < 4; j++) oacc[i][j] = 0.f;

    float rm0 = -1e30f, rm1 = -1e30f, rl0 = 0.f, rl1 = 0.f;
    int r0 = q0 + wid * 16 + g;
    int r1 = r0 + 8;
    const int mkind = CROSS ? g_mask_kind : 0;

    for (int kv0 = 0; kv0 < NK_; kv0 += 64) {
        __syncthreads();
        for (int idx = t; idx < 4096; idx += 128) {
            int r = idx >> 6, d = idx & 63;
            Ks[r][d] = f2tf32(Kp[(size_t)(kv0 + r) * kv_rs + d]);
        }
        for (int idx = t; idx < 2048; idx += 128) {
            int d = idx & 63, j = idx >> 6;
            float v0 = Vg[(size_t)(kv0 + 2 * j)     * kv_rs + d];
            float v1 = Vg[(size_t)(kv0 + 2 * j + 1) * kv_rs + d];
            Vp[d][j] = pack_bf16x2(v0, v1);
        }
        __syncthreads();

        float sacc[8][4];
        #pragma unroll
        for (int i = 0; i < 8; i++)
            #pragma unroll
            for (int j = 0; j < 4; j++) sacc[i][j] = 0.f;
        #pragma unroll
        for (int k8 = 0; k8 < 8; k8++) {
            int c0 = k8 * 8 + c;
            #pragma unroll
            for (int nt = 0; nt < 8; nt++) {
                int n = nt * 8 + g;
                uint32_t bf[2] = {Ks[n][c0], Ks[n][c0 + 4]};
                mma_tf32(sacc[nt], qf[k8], bf);
            }
        }

        #pragma unroll
        for (int nt = 0; nt < 8; nt++) {
            int col = kv0 + nt * 8 + 2 * c;
            float s0 = sacc[nt][0] * ATT_SCALE, s1 = sacc[nt][1] * ATT_SCALE;
            float s2 = sacc[nt][2] * ATT_SCALE, s3 = sacc[nt][3] * ATT_SCALE;
            if (CROSS) {
                size_t base = (size_t)(b * HH + h) * NQ_;
                float2 sv0 = *(const float2*)(sims + (base + r0) * NK_ + col);
                float2 sv1 = *(const float2*)(sims + (base + r1) * NK_ + col);
                float2 mm0 = *(const float2*)(simmean + ((size_t)b * NQ_ + r0) * NK_ + col);
                float2 mm1 = *(const float2*)(simmean + ((size_t)b * NQ_ + r1) * NK_ + col);
                s0 += sv0.x - mm0.x; s1 += sv0.y - mm0.y;
                s2 += sv1.x - mm1.x; s3 += sv1.y - mm1.y;
                size_t mi0 = (size_t)r0 * NK_ + col, mi1 = (size_t)r1 * NK_ + col;
                bool k0a, k0b, k1a, k1b;
                if (mkind == 0) {
                    const unsigned char* m = (const unsigned char*)maskp;
                    k0a = m[mi0] != 0; k0b = m[mi0 + 1] != 0;
                    k1a = m[mi1] != 0; k1b = m[mi1 + 1] != 0;
                } else if (mkind == 1) {
                    const int* m = (const int*)maskp;
                    k0a = m[mi0] != 0; k0b = m[mi0 + 1] != 0;
                    k1a = m[mi1] != 0; k1b = m[mi1 + 1] != 0;
                } else {
                    const float* m = (const float*)maskp;
                    k0a = m[mi0] != 0.f; k0b = m[mi0 + 1] != 0.f;
                    k1a = m[mi1] != 0.f; k1b = m[mi1 + 1] != 0.f;
                }
                if (!k0a) s0 = -1e30f;
                if (!k0b) s1 = -1e30f;
                if (!k1a) s2 = -1e30f;
                if (!k1b) s3 = -1e30f;
            }
            sacc[nt][0] = s0; sacc[nt][1] = s1; sacc[nt][2] = s2; sacc[nt][3] = s3;
        }

        float tm0 = -1e30f, tm1 = -1e30f;
        #pragma unroll
        for (int nt = 0; nt < 8; nt++) {
            tm0 = fmaxf(tm0, fmaxf(sacc[nt][0], sacc[nt][1]));
            tm1 = fmaxf(tm1, fmaxf(sacc[nt][2], sacc[nt][3]));
        }
        tm0 = fmaxf(tm0, __shfl_xor_sync(0xffffffffu, tm0, 1));
        tm0 = fmaxf(tm0, __shfl_xor_sync(0xffffffffu, tm0, 2));
        tm1 = fmaxf(tm1, __shfl_xor_sync(0xffffffffu, tm1, 1));
        tm1 = fmaxf(tm1, __shfl_xor_sync(0xffffffffu, tm1, 2));
        float nm0 = fmaxf(rm0, tm0), nm1 = fmaxf(rm1, tm1);
        float al0 = __expf(rm0 - nm0), al1 = __expf(rm1 - nm1);
        float sum0 = 0.f, sum1 = 0.f;
        #pragma unroll
        for (int nt = 0; nt < 8; nt++) {
            float p0 = __expf(sacc[nt][0] - nm0);
            float p1 = __expf(sacc[nt][1] - nm0);
            float p2 = __expf(sacc[nt][2] - nm1);
            float p3 = __expf(sacc[nt][3] - nm1);
            sum0 += p0 + p1; sum1 += p2 + p3;
            sacc[nt][0] = p0; sacc[nt][1] = p1; sacc[nt][2] = p2; sacc[nt][3] = p3;
        }
        sum0 += __shfl_xor_sync(0xffffffffu, sum0, 1);
        sum0 += __shfl_xor_sync(0xffffffffu, sum0, 2);
        sum1 += __shfl_xor_sync(0xffffffffu, sum1, 1);
        sum1 += __shfl_xor_sync(0xffffffffu, sum1, 2);
        rl0 = rl0 * al0 + sum0; rl1 = rl1 * al1 + sum1;
        rm0 = nm0; rm1 = nm1;
        #pragma unroll
        for (int i = 0; i < 8; i++) {
            oacc[i][0] *= al0; oacc[i][1] *= al0;
            oacc[i][2] *= al1; oacc[i][3] *= al1;
        }

        uint32_t pa[4][4];
        #pragma unroll
        for (int j = 0; j < 4; j++) {
            pa[j][0] = pack_bf16x2(sacc[2*j][0],     sacc[2*j][1]);
            pa[j][1] = pack_bf16x2(sacc[2*j][2],     sacc[2*j][3]);
            pa[j][2] = pack_bf16x2(sacc[2*j + 1][0], sacc[2*j + 1][1]);
            pa[j][3] = pack_bf16x2(sacc[2*j + 1][2], sacc[2*j + 1][3]);
        }

        #pragma unroll
        for (int ntd = 0; ntd < 8; ntd++) {
            int n = ntd * 8 + g;
            #pragma unroll
            for (int j = 0; j < 4; j++) {
                uint32_t bb[2] = {Vp[n][j * 8 + c], Vp[n][j * 8 + c + 4]};
                mma_bf16(oacc[ntd], pa[j], bb);
            }
        }
    }

    float inv0 = 1.f / rl0, inv1 = 1.f / rl1;
    #pragma unroll
    for (int ntd = 0; ntd < 8; ntd++) {
        int col = ntd * 8 + 2 * c;
        float* op0 = Ob + ((size_t)b * NQ_ + r0) * CC + h * DH_ + col;
        float* op1 = Ob + ((size_t)b * NQ_ + r1) * CC + h * DH_ + col;
        *(float2*)op0 = make_float2(oacc[ntd][0] * inv0, oacc[ntd][1] * inv0);
        *(float2*)op1 = make_float2(oacc[ntd][2] * inv1, oacc[ntd][3] * inv1);
    }
}

// ---------------------------------------------------------------------------
// similarities head-mean
// ---------------------------------------------------------------------------
__global__ __launch_bounds__(256)
void simmean_kernel(const float* __restrict__ sims)
{
    size_t idx = (size_t)blockIdx.x * 256 + threadIdx.x;
    int b = (int)(idx >> 20);
    size_t qk = idx & 1048575u;
    float s = 0.f;
    #pragma unroll
    for (int h = 0; h < HH; h++)
        s += sims[(((size_t)(b * HH + h)) << 20) + qk];
    g_simmean[idx] = s * (1.0f / HH);
}

// ---------------------------------------------------------------------------
// Mask dtype detection
// ---------------------------------------------------------------------------
__global__ void detect_mask_kernel(const unsigned char* __restrict__ m)
{
    if (threadIdx.x == 0 && blockIdx.x == 0) {
        int ones = 0, nonbin = 0;
        for (int i = 0; i < 4096; i++) {
            unsigned char v = m[i];
            if (v > 1) nonbin = 1;
            if (v == 1) ones++;
        }
        g_mask_kind = nonbin ? 2 : (ones > 1228 ? 0 : 1);
    }
}

// ---------------------------------------------------------------------------
// float4 copy (y passthrough)
// ---------------------------------------------------------------------------
__global__ __launch_bounds__(256)
void copy4_kernel(const float4* __restrict__ s, float4* __restrict__ d, int n4)
{
    int i = blockIdx.x * 256 + threadIdx.x;
    if (i < n4) d[i] = s[i];
}

// ---------------------------------------------------------------------------
// Launch
// ---------------------------------------------------------------------------
extern "C" void kernel_launch(void* const* d_in, const int* in_sizes, int n_in,
                              void* d_out, int out_size)
{
    const float* x       = (const float*)d_in[0];
    const float* y       = (const float*)d_in[1];
    const void*  mask    = d_in[4];
    const float* sims    = (const float*)d_in[5];
    const float* ln1_g   = (const float*)d_in[6];
    const float* ln1_b   = (const float*)d_in[7];
    const float* ln2_g   = (const float*)d_in[8];
    const float* ln2_b   = (const float*)d_in[9];
    const float* ln3_g   = (const float*)d_in[10];
    const float* ln3_b   = (const float*)d_in[11];
    const float* lny_g   = (const float*)d_in[12];
    const float* lny_b   = (const float*)d_in[13];
    const float* qkv_w   = (const float*)d_in[14];
    const float* aproj_w = (const float*)d_in[15];
    const float* aproj_b = (const float*)d_in[16];
    const float* pq_w    = (const float*)d_in[17];
    const float* pk_w    = (const float*)d_in[18];
    const float* pv_w    = (const float*)d_in[19];
    const float* cproj_w = (const float*)d_in[20];
    const float* cproj_b = (const float*)d_in[21];
    const float* fc1_w   = (const float*)d_in[22];
    const float* fc1_b   = (const float*)d_in[23];
    const float* fc2_w   = (const float*)d_in[24];
    const float* fc2_b   = (const float*)d_in[25];
    float* out = (float*)d_out;

    float *p_xn, *p_qkv, *p_sa, *p_x1, *p_yn, *p_cq, *p_ck, *p_cv, *p_x2, *p_hid, *p_sm;
    cudaGetSymbolAddress((void**)&p_xn,  g_xn);
    cudaGetSymbolAddress((void**)&p_qkv, g_qkv);
    cudaGetSymbolAddress((void**)&p_sa,  g_sa);
    cudaGetSymbolAddress((void**)&p_x1,  g_x1);
    cudaGetSymbolAddress((void**)&p_yn,  g_yn);
    cudaGetSymbolAddress((void**)&p_cq,  g_cq);
    cudaGetSymbolAddress((void**)&p_ck,  g_ck);
    cudaGetSymbolAddress((void**)&p_cv,  g_cv);
    cudaGetSymbolAddress((void**)&p_x2,  g_x2);
    cudaGetSymbolAddress((void**)&p_hid, g_hid);
    cudaGetSymbolAddress((void**)&p_sm,  g_simmean);

    // ---- self-attention ----
    ln_kernel<<<NTOK, 256>>>(x, ln1_g, ln1_b, p_xn);
    gemm_tc3<false><<<dim3(3 * CC / 128, NTOK / 128), 256>>>(
        p_xn, qkv_w, nullptr, nullptr, p_qkv, NTOK, 3 * CC, CC);
    attn_tc<false><<<dim3(NQ_ / 64, HH, BB), 128>>>(
        p_qkv, p_qkv + CC, p_qkv + 2 * CC,
        3 * CC, 3 * CC,
        (long long)NQ_ * 3 * CC, DH_,
        (long long)NQ_ * 3 * CC, DH_,
        p_sa, nullptr, nullptr, nullptr);
    gemm_tc3<false><<<dim3(CC / 128, NTOK / 128), 256>>>(
        p_sa, aproj_w, aproj_b, x, p_x1, NTOK, CC, CC);

    // ---- cross-attention ----
    ln_kernel<<<NTOK, 256>>>(y,    lny_g, lny_b, p_yn);
    ln_kernel<<<NTOK, 256>>>(p_x1, ln2_g, ln2_b, p_xn);
    gemm_tc3<false><<<dim3(CC / 128, NTOK / 128), 256>>>(
        p_xn, pq_w, nullptr, nullptr, p_cq, NTOK, CC, CC);
    gemm_tc3<false><<<dim3(CC / 128, NTOK / 128), 256>>>(
        p_yn, pk_w, nullptr, nullptr, p_ck, NTOK, CC, CC);
    gemm_tc3<false><<<dim3(CC / 128, NTOK / 128), 256>>>(
        p_yn, pv_w, nullptr, nullptr, p_cv, NTOK, CC, CC);
    simmean_kernel<<<(BB * NQ_ * NK_) / 256, 256>>>(sims);
    detect_mask_kernel<<<1, 1>>>((const unsigned char*)mask);
    attn_tc<true><<<dim3(NQ_ / 64, HH, BB), 128>>>(
        p_cq, p_ck, p_cv,
        CC, CC,
        (long long)NQ_ * CC, DH_,
        (long long)NQ_ * CC, DH_,
        p_sa, sims, p_sm, mask);
    gemm_tc3<false><<<dim3(CC / 128, NTOK / 128), 256>>>(
        p_sa, cproj_w, cproj_b, p_x1, p_x2, NTOK, CC, CC);

    // ---- MLP ----
    ln_kernel<<<NTOK, 256>>>(p_x2, ln3_g, ln3_b, p_xn);
    gemm_tc3<true><<<dim3(HID / 128, NTOK / 128), 256>>>(
        p_xn, fc1_w, fc1_b, nullptr, p_hid, NTOK, HID, CC);
    gemm_tc3<false><<<dim3(CC / 128, NTOK / 128), 256>>>(
        p_hid, fc2_w, fc2_b, p_x2, out, NTOK, CC, HID);

    // ---- y passthrough (second half of output), only if out holds (x, y) ----
    if (out_size >= 2 * NTOK * CC) {
        copy4_kernel<<<(NTOK * CC / 4 + 255) / 256, 256>>>(
            (const float4*)y, (float4*)(out + (size_t)NTOK * CC), NTOK * CC / 4);
    }
}